// round 5
// baseline (speedup 1.0000x reference)
#include <cuda_runtime.h>

#define T_SEQ 256
#define NH 8
#define DHD 64
#define DMODEL 512
#define NPROJ 2560   // 5 * 512

// ---------------- scratch ----------------
__device__ float g_proj[T_SEQ * NPROJ];            // [t, 2560]
__device__ float g_M[NH * T_SEQ * DHD * DHD];      // [n, q, k, j]
__device__ float g_G[NH * T_SEQ * DHD * DHD];      // [n, q, a, c]
__device__ float g_l[NH * T_SEQ];                  // softmax denominators
__device__ float g_z[T_SEQ * DMODEL];              // [q, n*64+e] (unnormalized accum)

// ---------------- K0: zero z ----------------
__global__ __launch_bounds__(256) void zero_z_kernel() {
    g_z[blockIdx.x * 256 + threadIdx.x] = 0.f;
}

// ---------------- K1: C[M,N] = A[M,K] @ B[K,N] + bias ----------------
__global__ __launch_bounds__(256) void gemm_nn_bias_kernel(
    const float* __restrict__ A, const float* __restrict__ B,
    const float* __restrict__ bias, float* __restrict__ C,
    int M, int N, int K) {
    __shared__ float AsT[32 * 68];   // k-major: [k][m]
    __shared__ float Bs[32 * 68];    // [k][n]
    const int tid = threadIdx.x;
    const int bm = blockIdx.y * 64;
    const int bn = blockIdx.x * 64;
    const int r0 = (tid & 15) * 4;
    const int c0 = (tid >> 4) * 4;
    const int arow = tid >> 3;
    const int acol = (tid & 7) * 4;
    const int brow = tid >> 4;
    const int bcol = (tid & 15) * 4;
    float acc[4][4] = {};
    for (int k0 = 0; k0 < K; k0 += 32) {
#pragma unroll
        for (int rr = 0; rr < 2; rr++) {
            int r = arow + rr * 32;
            float4 v = *reinterpret_cast<const float4*>(&A[(size_t)(bm + r) * K + k0 + acol]);
            AsT[(acol + 0) * 68 + r] = v.x; AsT[(acol + 1) * 68 + r] = v.y;
            AsT[(acol + 2) * 68 + r] = v.z; AsT[(acol + 3) * 68 + r] = v.w;
        }
#pragma unroll
        for (int rr = 0; rr < 2; rr++) {
            float4 v = *reinterpret_cast<const float4*>(&B[(size_t)(k0 + brow + rr * 16) * N + bn + bcol]);
            *reinterpret_cast<float4*>(&Bs[(brow + rr * 16) * 68 + bcol]) = v;
        }
        __syncthreads();
#pragma unroll
        for (int kk = 0; kk < 32; kk++) {
            float4 a = *reinterpret_cast<const float4*>(&AsT[kk * 68 + r0]);
            float4 b = *reinterpret_cast<const float4*>(&Bs[kk * 68 + c0]);
            float av[4] = {a.x, a.y, a.z, a.w};
            float bv[4] = {b.x, b.y, b.z, b.w};
#pragma unroll
            for (int i = 0; i < 4; i++)
#pragma unroll
                for (int j = 0; j < 4; j++) acc[i][j] += av[i] * bv[j];
        }
        __syncthreads();
    }
    float4 bb = *reinterpret_cast<const float4*>(&bias[bn + c0]);
#pragma unroll
    for (int i = 0; i < 4; i++) {
        float4 o = make_float4(acc[i][0] + bb.x, acc[i][1] + bb.y, acc[i][2] + bb.z, acc[i][3] + bb.w);
        *reinterpret_cast<float4*>(&C[(size_t)(bm + r0 + i) * N + bn + c0]) = o;
    }
}

// ---------------- K2: M[n,q,kj] = sum_i qproj[q,i] * Wkq[n,kj,i] ----------------
__global__ __launch_bounds__(256) void compute_M_kernel(const float* __restrict__ Wkq) {
    __shared__ float AsT[64 * 68];   // [i][q]
    __shared__ float BsT[64 * 68];   // [i][kj]
    const int n = blockIdx.z;
    const int bq = blockIdx.y * 64;
    const int bkj = blockIdx.x * 64;
    const int tid = threadIdx.x;
    const int row = tid >> 4;
    const int col = (tid & 15) * 4;
#pragma unroll
    for (int rr = 0; rr < 4; rr++) {
        int r = row + rr * 16;
        float4 va = *reinterpret_cast<const float4*>(&g_proj[(size_t)(bq + r) * NPROJ + 1024 + n * 64 + col]);
        AsT[(col + 0) * 68 + r] = va.x; AsT[(col + 1) * 68 + r] = va.y;
        AsT[(col + 2) * 68 + r] = va.z; AsT[(col + 3) * 68 + r] = va.w;
        float4 vb = *reinterpret_cast<const float4*>(&Wkq[(size_t)n * 262144 + (size_t)(bkj + r) * 64 + col]);
        BsT[(col + 0) * 68 + r] = vb.x; BsT[(col + 1) * 68 + r] = vb.y;
        BsT[(col + 2) * 68 + r] = vb.z; BsT[(col + 3) * 68 + r] = vb.w;
    }
    __syncthreads();
    const int q0 = (tid & 15) * 4;
    const int kj0 = (tid >> 4) * 4;
    float acc[4][4] = {};
#pragma unroll 8
    for (int i = 0; i < 64; i++) {
        float4 a = *reinterpret_cast<const float4*>(&AsT[i * 68 + q0]);
        float4 b = *reinterpret_cast<const float4*>(&BsT[i * 68 + kj0]);
        float av[4] = {a.x, a.y, a.z, a.w};
        float bv[4] = {b.x, b.y, b.z, b.w};
#pragma unroll
        for (int ii = 0; ii < 4; ii++)
#pragma unroll
            for (int jj = 0; jj < 4; jj++) acc[ii][jj] += av[ii] * bv[jj];
    }
#pragma unroll
    for (int ii = 0; ii < 4; ii++) {
        float4 o = make_float4(acc[ii][0], acc[ii][1], acc[ii][2], acc[ii][3]);
        *reinterpret_cast<float4*>(&g_M[(size_t)(n * T_SEQ + bq + q0 + ii) * 4096 + bkj + kj0]) = o;
    }
}

// ---------------- K3: main attention (256 threads, vectorized p) ----------------
#define OFF_K1T 0           // [64][260] k1T (k,p) phase1; v1s [256][64] phase3
#define OFF_BT  16640       // [64][256] B transposed (j, p)
#define OFF_ET  33024       // [64][256] E transposed (t, p); RT (c,p) phase3
#define OFF_C   49408       // [64][64] M (k,j) phase1 (stride 64); k2T [j][t] stride 68 phase2
#define OFF_V2  53760       // [64][64] v2 (t,c) phase2
#define OFF_RED 57856       // [8]
#define ATTN_SMEM_FLOATS 57864
#define ATTN_SMEM_BYTES (ATTN_SMEM_FLOATS * 4)

// NT = ceil(P/64): number of 64-wide p/t tiles.
template <int NT>
__device__ __forceinline__ void attn_body(float* sm, int n, int q, int tid) {
    float* k1T = sm + OFF_K1T;   // stride 260
    float* BT  = sm + OFF_BT;    // stride 256
    float* ET  = sm + OFF_ET;    // stride 256
    float* Cr  = sm + OFF_C;     // M stride 64 / k2T stride 68
    float* v2s = sm + OFF_V2;    // stride 64
    float* red = sm + OFF_RED;

    const int P = q + 1;
    const int pl = tid & 31;
    const int tg = tid >> 5;            // warp 0..7
    const int lp = (pl & 15) * 4;       // lane's 4 consecutive p base
    const int c4 = tg * 8 + (pl >> 4) * 4;  // 4-wide c/t/j slot

    // ---- load M into Cr (stride 64) ----
    {
        const float* Mg = g_M + (size_t)(n * T_SEQ + q) * 4096;
#pragma unroll
        for (int r = 0; r < 4; r++) {
            int off = (tid + r * 256) * 4;
            *reinterpret_cast<float4*>(&Cr[off]) = *reinterpret_cast<const float4*>(&Mg[off]);
        }
    }
    // ---- load k1 transposed [k][p] (stride 260), zero past P ----
    {
        const int rr = tid >> 4;            // 0..15
        const int iv = (tid & 15) * 4;
#pragma unroll
        for (int pass = 0; pass < NT * 4; pass++) {
            int p = pass * 16 + rr;
            float4 v = make_float4(0.f, 0.f, 0.f, 0.f);
            if (p < P) v = *reinterpret_cast<const float4*>(&g_proj[(size_t)p * NPROJ + n * 64 + iv]);
            k1T[(iv + 0) * 260 + p] = v.x;
            k1T[(iv + 1) * 260 + p] = v.y;
            k1T[(iv + 2) * 260 + p] = v.z;
            k1T[(iv + 3) * 260 + p] = v.w;
        }
    }
    __syncthreads();

    // ---- phase 1: B[p,j] = sum_k k1[p,k]*M[k,j]; store BT[j][p] (float4 over p) ----
    {
#pragma unroll
        for (int i = 0; i < NT; i++) {
            float acc1[4][4] = {};
#pragma unroll 8
            for (int k = 0; k < 64; k++) {
                float4 a = *reinterpret_cast<const float4*>(&k1T[k * 260 + lp + 64 * i]);
                float4 b = *reinterpret_cast<const float4*>(&Cr[k * 64 + c4]);
                float av[4] = {a.x, a.y, a.z, a.w};
                float bv[4] = {b.x, b.y, b.z, b.w};
#pragma unroll
                for (int kk = 0; kk < 4; kk++)
#pragma unroll
                    for (int jj = 0; jj < 4; jj++) acc1[kk][jj] += av[kk] * bv[jj];
            }
#pragma unroll
            for (int jj = 0; jj < 4; jj++) {
                float4 o = make_float4(acc1[0][jj], acc1[1][jj], acc1[2][jj], acc1[3][jj]);
                *reinterpret_cast<float4*>(&BT[(c4 + jj) * 256 + lp + 64 * i]) = o;
            }
        }
    }
    __syncthreads();

    // ---- phase 2: stream t-tiles ----
    float R[NT][4][4];
#pragma unroll
    for (int i = 0; i < NT; i++)
#pragma unroll
        for (int k = 0; k < 4; k++)
#pragma unroll
            for (int j = 0; j < 4; j++) R[i][k][j] = 0.f;
    float lsum = 0.f;
#pragma unroll 1
    for (int tt = 0; tt < NT; tt++) {
        const int t0 = tt * 64;
        {   // load k2 transposed [j][t] (Cr stride 68) + v2 [t][c], zero past P
            const int rr = tid >> 4;
            const int iv = (tid & 15) * 4;
#pragma unroll
            for (int pass = 0; pass < 4; pass++) {
                int t = pass * 16 + rr;
                int gt = t0 + t;
                float4 a = make_float4(0.f, 0.f, 0.f, 0.f);
                float4 b = make_float4(0.f, 0.f, 0.f, 0.f);
                if (gt < P) {
                    a = *reinterpret_cast<const float4*>(&g_proj[(size_t)gt * NPROJ + 512 + n * 64 + iv]);
                    b = *reinterpret_cast<const float4*>(&g_proj[(size_t)gt * NPROJ + 2048 + n * 64 + iv]);
                }
                Cr[(iv + 0) * 68 + t] = a.x;
                Cr[(iv + 1) * 68 + t] = a.y;
                Cr[(iv + 2) * 68 + t] = a.z;
                Cr[(iv + 3) * 68 + t] = a.w;
                *reinterpret_cast<float4*>(&v2s[t * 64 + iv]) = b;
            }
        }
        __syncthreads();
        // per p-group: S, exp, store ET[t][p]
#pragma unroll
        for (int i = 0; i < NT; i++) {
            float s[4][4] = {};
#pragma unroll 8
            for (int j = 0; j < 64; j++) {
                float4 a = *reinterpret_cast<const float4*>(&BT[j * 256 + lp + 64 * i]);
                float4 b = *reinterpret_cast<const float4*>(&Cr[j * 68 + c4]);
                float av[4] = {a.x, a.y, a.z, a.w};
                float bv[4] = {b.x, b.y, b.z, b.w};
#pragma unroll
                for (int kk = 0; kk < 4; kk++)
#pragma unroll
                    for (int jj = 0; jj < 4; jj++) s[kk][jj] += av[kk] * bv[jj];
            }
#pragma unroll
            for (int jj = 0; jj < 4; jj++) {
                int t = t0 + c4 + jj;
                float e[4];
#pragma unroll
                for (int kk = 0; kk < 4; kk++) {
                    int p = lp + kk + 64 * i;
                    e[kk] = (p < P && t < P) ? __expf(s[kk][jj] * 0.015625f) : 0.f;
                    lsum += e[kk];
                }
                *reinterpret_cast<float4*>(&ET[(c4 + jj) * 256 + lp + 64 * i]) =
                    make_float4(e[0], e[1], e[2], e[3]);
            }
        }
        __syncthreads();
        // R[p,c] += sum_t E[p,t] * v2[t,c]
#pragma unroll
        for (int i = 0; i < NT; i++) {
#pragma unroll 8
            for (int t = 0; t < 64; t++) {
                float4 a = *reinterpret_cast<const float4*>(&ET[t * 256 + lp + 64 * i]);
                float4 b = *reinterpret_cast<const float4*>(&v2s[t * 64 + c4]);
                float av[4] = {a.x, a.y, a.z, a.w};
                float bv[4] = {b.x, b.y, b.z, b.w};
#pragma unroll
                for (int kk = 0; kk < 4; kk++)
#pragma unroll
                    for (int jj = 0; jj < 4; jj++) R[i][kk][jj] += av[kk] * bv[jj];
            }
        }
        __syncthreads();
    }

    // ---- stage RT[c][p] into ET (float4 over p); load v1 [p][64] into k1T region ----
#pragma unroll
    for (int i = 0; i < NT; i++)
#pragma unroll
        for (int jj = 0; jj < 4; jj++) {
            float4 o = make_float4(R[i][0][jj], R[i][1][jj], R[i][2][jj], R[i][3][jj]);
            *reinterpret_cast<float4*>(&ET[(c4 + jj) * 256 + lp + 64 * i]) = o;
        }
    {
        float* v1s = k1T;   // [p][64]; rows >= P hold stale-but-finite data, matched with RT==0
        const int rr = tid >> 4;
        const int iv = (tid & 15) * 4;
#pragma unroll
        for (int pass = 0; pass < NT * 4; pass++) {
            int p = pass * 16 + rr;
            if (p < P) {
                float4 v = *reinterpret_cast<const float4*>(&g_proj[(size_t)p * NPROJ + 1536 + n * 64 + iv]);
                *reinterpret_cast<float4*>(&v1s[p * 64 + iv]) = v;
            }
        }
    }
    // lsum reduce
#pragma unroll
    for (int off = 16; off > 0; off >>= 1)
        lsum += __shfl_xor_sync(0xffffffffu, lsum, off);
    if (pl == 0) red[tg] = lsum;
    __syncthreads();
    if (tid == 0) {
        float total = 0.f;
#pragma unroll
        for (int w = 0; w < 8; w++) total += red[w];
        g_l[n * T_SEQ + q] = total;
    }

    // ---- phase 3: G[a,c] = sum_p v1[p,a] * RT[c,p], p stepped by 4 (both float4) ----
    {
        const float* v1s = k1T;
        const float* RT = ET;
        const int a0 = (tid & 15) * 4;
        const int c0 = (tid >> 4) * 4;
        float acc[4][4] = {};
#pragma unroll 4
        for (int p0 = 0; p0 < NT * 64; p0 += 4) {
            float4 av4[4], rv4[4];
#pragma unroll
            for (int k = 0; k < 4; k++) av4[k] = *reinterpret_cast<const float4*>(&v1s[(p0 + k) * 64 + a0]);
#pragma unroll
            for (int k = 0; k < 4; k++) rv4[k] = *reinterpret_cast<const float4*>(&RT[(c0 + k) * 256 + p0]);
#pragma unroll
            for (int k = 0; k < 4; k++) {
                float av[4] = {av4[k].x, av4[k].y, av4[k].z, av4[k].w};
                float rv[4] = {rv4[0].x, rv4[1].x, rv4[2].x, rv4[3].x};
                if (k == 1) { rv[0] = rv4[0].y; rv[1] = rv4[1].y; rv[2] = rv4[2].y; rv[3] = rv4[3].y; }
                if (k == 2) { rv[0] = rv4[0].z; rv[1] = rv4[1].z; rv[2] = rv4[2].z; rv[3] = rv4[3].z; }
                if (k == 3) { rv[0] = rv4[0].w; rv[1] = rv4[1].w; rv[2] = rv4[2].w; rv[3] = rv4[3].w; }
#pragma unroll
                for (int ka = 0; ka < 4; ka++)
#pragma unroll
                    for (int kc = 0; kc < 4; kc++) acc[ka][kc] += av[ka] * rv[kc];
            }
        }
        float* Gout = g_G + (size_t)(n * T_SEQ + q) * 4096;
#pragma unroll
        for (int ka = 0; ka < 4; ka++) {
            float4 o = make_float4(acc[ka][0], acc[ka][1], acc[ka][2], acc[ka][3]);
            *reinterpret_cast<float4*>(&Gout[(a0 + ka) * 64 + c0]) = o;
        }
    }
}

__global__ __launch_bounds__(256, 1) void attn_kernel() {
    extern __shared__ float sm[];
    const int bid = blockIdx.x;
    const int n = bid & 7;
    const int q = 255 - (bid >> 3);   // big-q CTAs first
    const int ntt = (q >> 6) + 1;
    switch (ntt) {
        case 1: attn_body<1>(sm, n, q, threadIdx.x); break;
        case 2: attn_body<2>(sm, n, q, threadIdx.x); break;
        case 3: attn_body<3>(sm, n, q, threadIdx.x); break;
        default: attn_body<4>(sm, n, q, threadIdx.x); break;
    }
}

// ---------------- K4: z_raw += G @ W_Vq (K-split, atomics) ----------------
__global__ __launch_bounds__(256) void out_v_kernel(const float* __restrict__ Wvq) {
    __shared__ float AsT[32 * 68];  // [k][q]
    __shared__ float Bs[32 * 68];   // [k][e]
    const int n = blockIdx.y;
    const int bq = blockIdx.x * 64;
    const int ks = blockIdx.z;
    const int tid = threadIdx.x;
    const int arow = tid >> 3, acol = (tid & 7) * 4;
    const int brow = tid >> 4, bcol = (tid & 15) * 4;
    const int q0 = (tid & 15) * 4, e0 = (tid >> 4) * 4;
    float acc[4][4] = {};
    for (int k0 = ks * 1024; k0 < ks * 1024 + 1024; k0 += 32) {
#pragma unroll
        for (int rr = 0; rr < 2; rr++) {
            int r = arow + rr * 32;
            float4 v = *reinterpret_cast<const float4*>(
                &g_G[(size_t)(n * T_SEQ + bq + r) * 4096 + k0 + acol]);
            AsT[(acol + 0) * 68 + r] = v.x; AsT[(acol + 1) * 68 + r] = v.y;
            AsT[(acol + 2) * 68 + r] = v.z; AsT[(acol + 3) * 68 + r] = v.w;
        }
#pragma unroll
        for (int rr = 0; rr < 2; rr++) {
            float4 v = *reinterpret_cast<const float4*>(
                &Wvq[(size_t)n * 262144 + (size_t)(k0 + brow + rr * 16) * 64 + bcol]);
            *reinterpret_cast<float4*>(&Bs[(brow + rr * 16) * 68 + bcol]) = v;
        }
        __syncthreads();
#pragma unroll
        for (int kk = 0; kk < 32; kk++) {
            float4 a = *reinterpret_cast<const float4*>(&AsT[kk * 68 + q0]);
            float4 b = *reinterpret_cast<const float4*>(&Bs[kk * 68 + e0]);
            float av[4] = {a.x, a.y, a.z, a.w};
            float bv[4] = {b.x, b.y, b.z, b.w};
#pragma unroll
            for (int i = 0; i < 4; i++)
#pragma unroll
                for (int j = 0; j < 4; j++) acc[i][j] += av[i] * bv[j];
        }
        __syncthreads();
    }
#pragma unroll
    for (int i = 0; i < 4; i++)
#pragma unroll
        for (int j = 0; j < 4; j++)
            atomicAdd(&g_z[(size_t)(bq + q0 + i) * DMODEL + n * 64 + e0 + j], acc[i][j]);
}

// ---------------- K5: out = (z_raw * 1/l) @ W_out + b_out ----------------
__global__ __launch_bounds__(256) void gemm_out_kernel(
    const float* __restrict__ Wout, const float* __restrict__ bout, float* __restrict__ C) {
    __shared__ float AsT[32 * 68];  // [k][m]
    __shared__ float Bs[32 * 68];   // [k][n]
    const int tid = threadIdx.x;
    const int bm = blockIdx.y * 64;
    const int bn = blockIdx.x * 64;
    const int r0 = (tid & 15) * 4;
    const int c0 = (tid >> 4) * 4;
    const int arow = tid >> 3, acol = (tid & 7) * 4;
    const int brow = tid >> 4, bcol = (tid & 15) * 4;
    float acc[4][4] = {};
    for (int k0 = 0; k0 < DMODEL; k0 += 32) {
#pragma unroll
        for (int rr = 0; rr < 2; rr++) {
            int r = bm + arow + rr * 32;
            int gk = k0 + acol;
            float invl = 1.f / g_l[(gk >> 6) * T_SEQ + r];
            float4 v = *reinterpret_cast<const float4*>(&g_z[(size_t)r * DMODEL + gk]);
            AsT[(acol + 0) * 68 + arow + rr * 32] = v.x * invl;
            AsT[(acol + 1) * 68 + arow + rr * 32] = v.y * invl;
            AsT[(acol + 2) * 68 + arow + rr * 32] = v.z * invl;
            AsT[(acol + 3) * 68 + arow + rr * 32] = v.w * invl;
        }
#pragma unroll
        for (int rr = 0; rr < 2; rr++) {
            float4 v = *reinterpret_cast<const float4*>(&Wout[(size_t)(k0 + brow + rr * 16) * DMODEL + bn + bcol]);
            *reinterpret_cast<float4*>(&Bs[(brow + rr * 16) * 68 + bcol]) = v;
        }
        __syncthreads();
#pragma unroll
        for (int kk = 0; kk < 32; kk++) {
            float4 a = *reinterpret_cast<const float4*>(&AsT[kk * 68 + r0]);
            float4 b = *reinterpret_cast<const float4*>(&Bs[kk * 68 + c0]);
            float av[4] = {a.x, a.y, a.z, a.w};
            float bv[4] = {b.x, b.y, b.z, b.w};
#pragma unroll
            for (int i = 0; i < 4; i++)
#pragma unroll
                for (int j = 0; j < 4; j++) acc[i][j] += av[i] * bv[j];
        }
        __syncthreads();
    }
    float4 bb = *reinterpret_cast<const float4*>(&bout[bn + c0]);
#pragma unroll
    for (int i = 0; i < 4; i++) {
        float4 o = make_float4(acc[i][0] + bb.x, acc[i][1] + bb.y, acc[i][2] + bb.z, acc[i][3] + bb.w);
        *reinterpret_cast<float4*>(&C[(size_t)(bm + r0 + i) * DMODEL + bn + c0]) = o;
    }
}

// ---------------- launch ----------------
extern "C" void kernel_launch(void* const* d_in, const int* in_sizes, int n_in,
                              void* d_out, int out_size) {
    const float* x       = (const float*)d_in[0];
    const float* Wkkqvv  = (const float*)d_in[1];
    const float* bkkqvv  = (const float*)d_in[2];
    const float* WKq     = (const float*)d_in[3];
    const float* WVq     = (const float*)d_in[4];
    const float* Wout    = (const float*)d_in[5];
    const float* bout    = (const float*)d_in[6];
    float* out = (float*)d_out;

    float* proj_ptr = nullptr;
    cudaGetSymbolAddress((void**)&proj_ptr, g_proj);

    cudaFuncSetAttribute(attn_kernel, cudaFuncAttributeMaxDynamicSharedMemorySize, ATTN_SMEM_BYTES);

    zero_z_kernel<<<T_SEQ * DMODEL / 256, 256>>>();
    gemm_nn_bias_kernel<<<dim3(NPROJ / 64, T_SEQ / 64), 256>>>(x, Wkkqvv, bkkqvv, proj_ptr,
                                                               T_SEQ, NPROJ, DMODEL);
    compute_M_kernel<<<dim3(64, 4, NH), 256>>>(WKq);
    attn_kernel<<<NH * T_SEQ, 256, ATTN_SMEM_BYTES>>>();
    out_v_kernel<<<dim3(4, NH, 4), 256>>>(WVq);
    gemm_out_kernel<<<dim3(DMODEL / 64, T_SEQ / 64), 256>>>(Wout, bout, out);
}

// round 6
// speedup vs baseline: 1.0582x; 1.0582x over previous
#include <cuda_runtime.h>

#define T_SEQ 256
#define NH 8
#define DHD 64
#define DMODEL 512
#define NPROJ 2560   // 5 * 512

// ---------------- scratch ----------------
__device__ float g_proj[T_SEQ * NPROJ];            // [t, 2560]
__device__ float g_M[NH * T_SEQ * DHD * DHD];      // [n, q, k, j]
__device__ float g_G[NH * T_SEQ * DHD * DHD];      // [n, q, a, c]
__device__ float g_l[NH * T_SEQ];                  // softmax denominators
__device__ float g_z[T_SEQ * DMODEL];              // [q, n*64+e] (unnormalized accum)

// ---------------- K0: zero z ----------------
__global__ __launch_bounds__(256) void zero_z_kernel() {
    g_z[blockIdx.x * 256 + threadIdx.x] = 0.f;
}

// ---------------- K1: C[M,N] = A[M,K] @ B[K,N] + bias ----------------
__global__ __launch_bounds__(256) void gemm_nn_bias_kernel(
    const float* __restrict__ A, const float* __restrict__ B,
    const float* __restrict__ bias, float* __restrict__ C,
    int M, int N, int K) {
    __shared__ float AsT[32 * 68];   // k-major: [k][m]
    __shared__ float Bs[32 * 68];    // [k][n]
    const int tid = threadIdx.x;
    const int bm = blockIdx.y * 64;
    const int bn = blockIdx.x * 64;
    const int r0 = (tid & 15) * 4;
    const int c0 = (tid >> 4) * 4;
    const int arow = tid >> 3;
    const int acol = (tid & 7) * 4;
    const int brow = tid >> 4;
    const int bcol = (tid & 15) * 4;
    float acc[4][4] = {};
    for (int k0 = 0; k0 < K; k0 += 32) {
#pragma unroll
        for (int rr = 0; rr < 2; rr++) {
            int r = arow + rr * 32;
            float4 v = *reinterpret_cast<const float4*>(&A[(size_t)(bm + r) * K + k0 + acol]);
            AsT[(acol + 0) * 68 + r] = v.x; AsT[(acol + 1) * 68 + r] = v.y;
            AsT[(acol + 2) * 68 + r] = v.z; AsT[(acol + 3) * 68 + r] = v.w;
        }
#pragma unroll
        for (int rr = 0; rr < 2; rr++) {
            float4 v = *reinterpret_cast<const float4*>(&B[(size_t)(k0 + brow + rr * 16) * N + bn + bcol]);
            *reinterpret_cast<float4*>(&Bs[(brow + rr * 16) * 68 + bcol]) = v;
        }
        __syncthreads();
#pragma unroll
        for (int kk = 0; kk < 32; kk++) {
            float4 a = *reinterpret_cast<const float4*>(&AsT[kk * 68 + r0]);
            float4 b = *reinterpret_cast<const float4*>(&Bs[kk * 68 + c0]);
            float av[4] = {a.x, a.y, a.z, a.w};
            float bv[4] = {b.x, b.y, b.z, b.w};
#pragma unroll
            for (int i = 0; i < 4; i++)
#pragma unroll
                for (int j = 0; j < 4; j++) acc[i][j] += av[i] * bv[j];
        }
        __syncthreads();
    }
    float4 bb = *reinterpret_cast<const float4*>(&bias[bn + c0]);
#pragma unroll
    for (int i = 0; i < 4; i++) {
        float4 o = make_float4(acc[i][0] + bb.x, acc[i][1] + bb.y, acc[i][2] + bb.z, acc[i][3] + bb.w);
        *reinterpret_cast<float4*>(&C[(size_t)(bm + r0 + i) * N + bn + c0]) = o;
    }
}

// ---------------- K2: M[n,q,kj] = sum_i qproj[q,i] * Wkq[n,kj,i] ----------------
__global__ __launch_bounds__(256) void compute_M_kernel(const float* __restrict__ Wkq) {
    __shared__ float AsT[64 * 68];   // [i][q]
    __shared__ float BsT[64 * 68];   // [i][kj]
    const int n = blockIdx.z;
    const int bq = blockIdx.y * 64;
    const int bkj = blockIdx.x * 64;
    const int tid = threadIdx.x;
    const int row = tid >> 4;
    const int col = (tid & 15) * 4;
#pragma unroll
    for (int rr = 0; rr < 4; rr++) {
        int r = row + rr * 16;
        float4 va = *reinterpret_cast<const float4*>(&g_proj[(size_t)(bq + r) * NPROJ + 1024 + n * 64 + col]);
        AsT[(col + 0) * 68 + r] = va.x; AsT[(col + 1) * 68 + r] = va.y;
        AsT[(col + 2) * 68 + r] = va.z; AsT[(col + 3) * 68 + r] = va.w;
        float4 vb = *reinterpret_cast<const float4*>(&Wkq[(size_t)n * 262144 + (size_t)(bkj + r) * 64 + col]);
        BsT[(col + 0) * 68 + r] = vb.x; BsT[(col + 1) * 68 + r] = vb.y;
        BsT[(col + 2) * 68 + r] = vb.z; BsT[(col + 3) * 68 + r] = vb.w;
    }
    __syncthreads();
    const int q0 = (tid & 15) * 4;
    const int kj0 = (tid >> 4) * 4;
    float acc[4][4] = {};
#pragma unroll 8
    for (int i = 0; i < 64; i++) {
        float4 a = *reinterpret_cast<const float4*>(&AsT[i * 68 + q0]);
        float4 b = *reinterpret_cast<const float4*>(&BsT[i * 68 + kj0]);
        float av[4] = {a.x, a.y, a.z, a.w};
        float bv[4] = {b.x, b.y, b.z, b.w};
#pragma unroll
        for (int ii = 0; ii < 4; ii++)
#pragma unroll
            for (int jj = 0; jj < 4; jj++) acc[ii][jj] += av[ii] * bv[jj];
    }
#pragma unroll
    for (int ii = 0; ii < 4; ii++) {
        float4 o = make_float4(acc[ii][0], acc[ii][1], acc[ii][2], acc[ii][3]);
        *reinterpret_cast<float4*>(&g_M[(size_t)(n * T_SEQ + bq + q0 + ii) * 4096 + bkj + kj0]) = o;
    }
}

// ---------------- K3: main attention (256 threads, strided-p, chunked S) ----------------
#define OFF_K1T 0           // [64][257] k1T (k,p) phase1; v1s [256][64] phase3
#define OFF_BT  16448       // [64][256] B transposed (j, p)
#define OFF_ET  33024       // wait recomputed below
#undef OFF_BT
#undef OFF_ET
#define OFF_BT  16448       // [64][256]
#define OFF_ET  32832       // [64][256]
#define OFF_C   49216       // [64][64] M (stride 64) phase1; k2T [j][t] stride 68 phase2 (64*68=4352)
#define OFF_V2  53568       // [64][64] v2 (t,c)
#define OFF_RED 57664       // [8]
#define ATTN_SMEM_FLOATS 57672
#define ATTN_SMEM_BYTES (ATTN_SMEM_FLOATS * 4)

// NI = number of 32-wide p blocks = 2*ceil(P/64).
template <int NI>
__device__ __forceinline__ void attn_body(float* sm, int n, int q, int tid) {
    float* k1T = sm + OFF_K1T;   // stride 257
    float* BT  = sm + OFF_BT;    // stride 256
    float* ET  = sm + OFF_ET;    // stride 256
    float* Cr  = sm + OFF_C;     // M stride 64 / k2T stride 68
    float* v2s = sm + OFF_V2;    // stride 64
    float* red = sm + OFF_RED;

    const int P = q + 1;
    const int pl = tid & 31;          // lane -> p base
    const int tg = tid >> 5;          // warp
    const int c8 = tg * 8;            // warp's 8-wide c/t/j slot

    // ---- load M into Cr (stride 64) ----
    {
        const float* Mg = g_M + (size_t)(n * T_SEQ + q) * 4096;
#pragma unroll
        for (int r = 0; r < 4; r++) {
            int off = (tid + r * 256) * 4;
            *reinterpret_cast<float4*>(&Cr[off]) = *reinterpret_cast<const float4*>(&Mg[off]);
        }
    }
    // ---- load k1 transposed [k][p] (stride 257), zero past P ----
    {
        const int rr = tid >> 4;            // 0..15
        const int iv = (tid & 15) * 4;
#pragma unroll
        for (int pass = 0; pass < NI * 2; pass++) {
            int p = pass * 16 + rr;
            float4 v = make_float4(0.f, 0.f, 0.f, 0.f);
            if (p < P) v = *reinterpret_cast<const float4*>(&g_proj[(size_t)p * NPROJ + n * 64 + iv]);
            k1T[(iv + 0) * 257 + p] = v.x;
            k1T[(iv + 1) * 257 + p] = v.y;
            k1T[(iv + 2) * 257 + p] = v.z;
            k1T[(iv + 3) * 257 + p] = v.w;
        }
    }
    __syncthreads();

    // ---- phase 1: B[p,j] = sum_k k1[p,k]*M[k,j]; store BT[j][p] ----
    {
        float acc[NI][8];
#pragma unroll
        for (int i = 0; i < NI; i++)
#pragma unroll
            for (int j = 0; j < 8; j++) acc[i][j] = 0.f;
#pragma unroll 4
        for (int k = 0; k < 64; k++) {
            float a[NI];
#pragma unroll
            for (int i = 0; i < NI; i++) a[i] = k1T[k * 257 + pl + 32 * i];
            float4 b0 = *reinterpret_cast<const float4*>(&Cr[k * 64 + c8]);
            float4 b1 = *reinterpret_cast<const float4*>(&Cr[k * 64 + c8 + 4]);
            float b[8] = {b0.x, b0.y, b0.z, b0.w, b1.x, b1.y, b1.z, b1.w};
#pragma unroll
            for (int i = 0; i < NI; i++)
#pragma unroll
                for (int j = 0; j < 8; j++) acc[i][j] += a[i] * b[j];
        }
#pragma unroll
        for (int j = 0; j < 8; j++)
#pragma unroll
            for (int i = 0; i < NI; i++)
                BT[(c8 + j) * 256 + pl + 32 * i] = acc[i][j];
    }
    __syncthreads();

    // ---- phase 2: stream t-tiles ----
    float R[NI][8];
#pragma unroll
    for (int i = 0; i < NI; i++)
#pragma unroll
        for (int j = 0; j < 8; j++) R[i][j] = 0.f;
    float lsum = 0.f;
#pragma unroll 1
    for (int tt = 0; tt < NI / 2; tt++) {
        const int t0 = tt * 64;
        {   // load k2 transposed [j][t] into Cr (stride 68) + v2 [t][c], zero past P
            const int rr = tid >> 4;
            const int iv = (tid & 15) * 4;
#pragma unroll
            for (int pass = 0; pass < 4; pass++) {
                int t = pass * 16 + rr;
                int gt = t0 + t;
                float4 a = make_float4(0.f, 0.f, 0.f, 0.f);
                float4 b = make_float4(0.f, 0.f, 0.f, 0.f);
                if (gt < P) {
                    a = *reinterpret_cast<const float4*>(&g_proj[(size_t)gt * NPROJ + 512 + n * 64 + iv]);
                    b = *reinterpret_cast<const float4*>(&g_proj[(size_t)gt * NPROJ + 2048 + n * 64 + iv]);
                }
                Cr[(iv + 0) * 68 + t] = a.x;
                Cr[(iv + 1) * 68 + t] = a.y;
                Cr[(iv + 2) * 68 + t] = a.z;
                Cr[(iv + 3) * 68 + t] = a.w;
                *reinterpret_cast<float4*>(&v2s[t * 64 + iv]) = b;
            }
        }
        __syncthreads();
        // ---- S in chunks of 4 p-blocks (keeps register pressure low); exp inline ----
#pragma unroll
        for (int ih = 0; ih < NI; ih += 4) {
            float s[4][8];
#pragma unroll
            for (int i = 0; i < 4; i++)
#pragma unroll
                for (int j = 0; j < 8; j++) s[i][j] = 0.f;
#pragma unroll 4
            for (int j = 0; j < 64; j++) {
                float a[4];
#pragma unroll
                for (int i = 0; i < 4; i++)
                    if (ih + i < NI) a[i] = BT[j * 256 + pl + 32 * (ih + i)];
                float4 b0 = *reinterpret_cast<const float4*>(&Cr[j * 68 + c8]);
                float4 b1 = *reinterpret_cast<const float4*>(&Cr[j * 68 + c8 + 4]);
                float b[8] = {b0.x, b0.y, b0.z, b0.w, b1.x, b1.y, b1.z, b1.w};
#pragma unroll
                for (int i = 0; i < 4; i++)
                    if (ih + i < NI)
#pragma unroll
                        for (int jj = 0; jj < 8; jj++) s[i][jj] += a[i] * b[jj];
            }
            // exp + mask + store ET[t][p]
#pragma unroll
            for (int i = 0; i < 4; i++) {
                if (ih + i < NI) {
                    int p = pl + 32 * (ih + i);
#pragma unroll
                    for (int jj = 0; jj < 8; jj++) {
                        int t = t0 + c8 + jj;
                        float e = (p < P && t < P) ? __expf(s[i][jj] * 0.015625f) : 0.f;
                        lsum += e;
                        ET[(c8 + jj) * 256 + p] = e;
                    }
                }
            }
        }
        __syncthreads();
        // ---- R[p,c] += sum_t E[p,t] * v2[t,c] ----
#pragma unroll 4
        for (int t = 0; t < 64; t++) {
            float a[NI];
#pragma unroll
            for (int i = 0; i < NI; i++) a[i] = ET[t * 256 + pl + 32 * i];
            float4 b0 = *reinterpret_cast<const float4*>(&v2s[t * 64 + c8]);
            float4 b1 = *reinterpret_cast<const float4*>(&v2s[t * 64 + c8 + 4]);
            float b[8] = {b0.x, b0.y, b0.z, b0.w, b1.x, b1.y, b1.z, b1.w};
#pragma unroll
            for (int i = 0; i < NI; i++)
#pragma unroll
                for (int j = 0; j < 8; j++) R[i][j] += a[i] * b[j];
        }
        __syncthreads();
    }

    // ---- stage RT[c][p] (into ET) + load v1 (into k1T region) ----
#pragma unroll
    for (int j = 0; j < 8; j++)
#pragma unroll
        for (int i = 0; i < NI; i++)
            ET[(c8 + j) * 256 + pl + 32 * i] = R[i][j];
    {
        float* v1s = k1T;   // [256][64]; rows >= P never read in phase 3
        const int rr = tid >> 4;
        const int iv = (tid & 15) * 4;
#pragma unroll
        for (int pass = 0; pass < NI * 2; pass++) {
            int p = pass * 16 + rr;
            if (p < P) {
                float4 v = *reinterpret_cast<const float4*>(&g_proj[(size_t)p * NPROJ + 1536 + n * 64 + iv]);
                *reinterpret_cast<float4*>(&v1s[p * 64 + iv]) = v;
            }
        }
    }
    // lsum reduce
#pragma unroll
    for (int off = 16; off > 0; off >>= 1)
        lsum += __shfl_xor_sync(0xffffffffu, lsum, off);
    if (pl == 0) red[tg] = lsum;
    __syncthreads();
    if (tid == 0) {
        float total = 0.f;
#pragma unroll
        for (int w = 0; w < 8; w++) total += red[w];
        g_l[n * T_SEQ + q] = total;
    }

    // ---- phase 3: G[a,c] = sum_{p<P} v1[p,a] * RT[c,p] ----
    {
        const float* v1s = k1T;
        const float* RT = ET;
        const int a0 = (tid & 15) * 4;
        const int c0 = (tid >> 4) * 4;
        float acc[4][4] = {};
#pragma unroll 4
        for (int p = 0; p < P; p++) {
            float4 av = *reinterpret_cast<const float4*>(&v1s[p * 64 + a0]);
            float avv[4] = {av.x, av.y, av.z, av.w};
            float rv[4];
#pragma unroll
            for (int k = 0; k < 4; k++) rv[k] = RT[(c0 + k) * 256 + p];
#pragma unroll
            for (int ka = 0; ka < 4; ka++)
#pragma unroll
                for (int kc = 0; kc < 4; kc++) acc[ka][kc] += avv[ka] * rv[kc];
        }
        float* Gout = g_G + (size_t)(n * T_SEQ + q) * 4096;
#pragma unroll
        for (int ka = 0; ka < 4; ka++) {
            float4 o = make_float4(acc[ka][0], acc[ka][1], acc[ka][2], acc[ka][3]);
            *reinterpret_cast<float4*>(&Gout[(a0 + ka) * 64 + c0]) = o;
        }
    }
}

__global__ __launch_bounds__(256, 1) void attn_kernel() {
    extern __shared__ float sm[];
    const int bid = blockIdx.x;
    const int n = bid & 7;
    const int q = 255 - (bid >> 3);   // big-q CTAs first
    const int ntt = (q >> 6) + 1;
    switch (ntt) {
        case 1: attn_body<2>(sm, n, q, threadIdx.x); break;
        case 2: attn_body<4>(sm, n, q, threadIdx.x); break;
        case 3: attn_body<6>(sm, n, q, threadIdx.x); break;
        default: attn_body<8>(sm, n, q, threadIdx.x); break;
    }
}

// ---------------- K4: z_raw += G @ W_Vq (K-split, atomics) ----------------
__global__ __launch_bounds__(256) void out_v_kernel(const float* __restrict__ Wvq) {
    __shared__ float AsT[32 * 68];  // [k][q]
    __shared__ float Bs[32 * 68];   // [k][e]
    const int n = blockIdx.y;
    const int bq = blockIdx.x * 64;
    const int ks = blockIdx.z;
    const int tid = threadIdx.x;
    const int arow = tid >> 3, acol = (tid & 7) * 4;
    const int brow = tid >> 4, bcol = (tid & 15) * 4;
    const int q0 = (tid & 15) * 4, e0 = (tid >> 4) * 4;
    float acc[4][4] = {};
    for (int k0 = ks * 1024; k0 < ks * 1024 + 1024; k0 += 32) {
#pragma unroll
        for (int rr = 0; rr < 2; rr++) {
            int r = arow + rr * 32;
            float4 v = *reinterpret_cast<const float4*>(
                &g_G[(size_t)(n * T_SEQ + bq + r) * 4096 + k0 + acol]);
            AsT[(acol + 0) * 68 + r] = v.x; AsT[(acol + 1) * 68 + r] = v.y;
            AsT[(acol + 2) * 68 + r] = v.z; AsT[(acol + 3) * 68 + r] = v.w;
        }
#pragma unroll
        for (int rr = 0; rr < 2; rr++) {
            float4 v = *reinterpret_cast<const float4*>(
                &Wvq[(size_t)n * 262144 + (size_t)(k0 + brow + rr * 16) * 64 + bcol]);
            *reinterpret_cast<float4*>(&Bs[(brow + rr * 16) * 68 + bcol]) = v;
        }
        __syncthreads();
#pragma unroll
        for (int kk = 0; kk < 32; kk++) {
            float4 a = *reinterpret_cast<const float4*>(&AsT[kk * 68 + q0]);
            float4 b = *reinterpret_cast<const float4*>(&Bs[kk * 68 + e0]);
            float av[4] = {a.x, a.y, a.z, a.w};
            float bv[4] = {b.x, b.y, b.z, b.w};
#pragma unroll
            for (int i = 0; i < 4; i++)
#pragma unroll
                for (int j = 0; j < 4; j++) acc[i][j] += av[i] * bv[j];
        }
        __syncthreads();
    }
#pragma unroll
    for (int i = 0; i < 4; i++)
#pragma unroll
        for (int j = 0; j < 4; j++)
            atomicAdd(&g_z[(size_t)(bq + q0 + i) * DMODEL + n * 64 + e0 + j], acc[i][j]);
}

// ---------------- K5: out = (z_raw * 1/l) @ W_out + b_out ----------------
__global__ __launch_bounds__(256) void gemm_out_kernel(
    const float* __restrict__ Wout, const float* __restrict__ bout, float* __restrict__ C) {
    __shared__ float AsT[32 * 68];  // [k][m]
    __shared__ float Bs[32 * 68];   // [k][n]
    const int tid = threadIdx.x;
    const int bm = blockIdx.y * 64;
    const int bn = blockIdx.x * 64;
    const int r0 = (tid & 15) * 4;
    const int c0 = (tid >> 4) * 4;
    const int arow = tid >> 3, acol = (tid & 7) * 4;
    const int brow = tid >> 4, bcol = (tid & 15) * 4;
    float acc[4][4] = {};
    for (int k0 = 0; k0 < DMODEL; k0 += 32) {
#pragma unroll
        for (int rr = 0; rr < 2; rr++) {
            int r = bm + arow + rr * 32;
            int gk = k0 + acol;
            float invl = 1.f / g_l[(gk >> 6) * T_SEQ + r];
            float4 v = *reinterpret_cast<const float4*>(&g_z[(size_t)r * DMODEL + gk]);
            AsT[(acol + 0) * 68 + arow + rr * 32] = v.x * invl;
            AsT[(acol + 1) * 68 + arow + rr * 32] = v.y * invl;
            AsT[(acol + 2) * 68 + arow + rr * 32] = v.z * invl;
            AsT[(acol + 3) * 68 + arow + rr * 32] = v.w * invl;
        }
#pragma unroll
        for (int rr = 0; rr < 2; rr++) {
            float4 v = *reinterpret_cast<const float4*>(&Wout[(size_t)(k0 + brow + rr * 16) * DMODEL + bn + bcol]);
            *reinterpret_cast<float4*>(&Bs[(brow + rr * 16) * 68 + bcol]) = v;
        }
        __syncthreads();
#pragma unroll
        for (int kk = 0; kk < 32; kk++) {
            float4 a = *reinterpret_cast<const float4*>(&AsT[kk * 68 + r0]);
            float4 b = *reinterpret_cast<const float4*>(&Bs[kk * 68 + c0]);
            float av[4] = {a.x, a.y, a.z, a.w};
            float bv[4] = {b.x, b.y, b.z, b.w};
#pragma unroll
            for (int i = 0; i < 4; i++)
#pragma unroll
                for (int j = 0; j < 4; j++) acc[i][j] += av[i] * bv[j];
        }
        __syncthreads();
    }
    float4 bb = *reinterpret_cast<const float4*>(&bout[bn + c0]);
#pragma unroll
    for (int i = 0; i < 4; i++) {
        float4 o = make_float4(acc[i][0] + bb.x, acc[i][1] + bb.y, acc[i][2] + bb.z, acc[i][3] + bb.w);
        *reinterpret_cast<float4*>(&C[(size_t)(bm + r0 + i) * DMODEL + bn + c0]) = o;
    }
}

// ---------------- launch ----------------
extern "C" void kernel_launch(void* const* d_in, const int* in_sizes, int n_in,
                              void* d_out, int out_size) {
    const float* x       = (const float*)d_in[0];
    const float* Wkkqvv  = (const float*)d_in[1];
    const float* bkkqvv  = (const float*)d_in[2];
    const float* WKq     = (const float*)d_in[3];
    const float* WVq     = (const float*)d_in[4];
    const float* Wout    = (const float*)d_in[5];
    const float* bout    = (const float*)d_in[6];
    float* out = (float*)d_out;

    float* proj_ptr = nullptr;
    cudaGetSymbolAddress((void**)&proj_ptr, g_proj);

    cudaFuncSetAttribute(attn_kernel, cudaFuncAttributeMaxDynamicSharedMemorySize, ATTN_SMEM_BYTES);

    zero_z_kernel<<<T_SEQ * DMODEL / 256, 256>>>();
    gemm_nn_bias_kernel<<<dim3(NPROJ / 64, T_SEQ / 64), 256>>>(x, Wkkqvv, bkkqvv, proj_ptr,
                                                               T_SEQ, NPROJ, DMODEL);
    compute_M_kernel<<<dim3(64, 4, NH), 256>>>(WKq);
    attn_kernel<<<NH * T_SEQ, 256, ATTN_SMEM_BYTES>>>();
    out_v_kernel<<<dim3(4, NH, 4), 256>>>(WVq);
    gemm_out_kernel<<<dim3(DMODEL / 64, T_SEQ / 64), 256>>>(Wout, bout, out);
}

// round 7
// speedup vs baseline: 1.1472x; 1.0841x over previous
#include <cuda_runtime.h>

#define T_SEQ 256
#define NH 8
#define DHD 64
#define DMODEL 512
#define NPROJ 2560   // 5 * 512

// ---------------- scratch ----------------
__device__ float g_proj[T_SEQ * NPROJ];            // [t, 2560]
__device__ float g_M[NH * T_SEQ * DHD * DHD];      // [n, q, k, j]
__device__ float g_Ga[NH * T_SEQ * DHD * DHD];     // [n, q, a, c] p-half 0
__device__ float g_Gb[NH * T_SEQ * DHD * DHD];     // [n, q, a, c] p-half 1
__device__ float g_l[2 * NH * T_SEQ];              // softmax denominator partials
__device__ float g_z[T_SEQ * DMODEL];              // [q, n*64+e] (unnormalized accum)

// ---------------- K0: zero z + l ----------------
#define NZERO (T_SEQ * DMODEL + 2 * NH * T_SEQ)    // 131072 + 4096 = 135168
__global__ __launch_bounds__(256) void zero_kernel() {
    int i = blockIdx.x * 256 + threadIdx.x;
    if (i < T_SEQ * DMODEL) g_z[i] = 0.f;
    else g_l[i - T_SEQ * DMODEL] = 0.f;
}

// ---------------- K1: C[M,N] = A[M,K] @ B[K,N] + bias ----------------
__global__ __launch_bounds__(256) void gemm_nn_bias_kernel(
    const float* __restrict__ A, const float* __restrict__ B,
    const float* __restrict__ bias, float* __restrict__ C,
    int M, int N, int K) {
    __shared__ float AsT[32 * 68];   // k-major: [k][m]
    __shared__ float Bs[32 * 68];    // [k][n]
    const int tid = threadIdx.x;
    const int bm = blockIdx.y * 64;
    const int bn = blockIdx.x * 64;
    const int r0 = (tid & 15) * 4;
    const int c0 = (tid >> 4) * 4;
    const int arow = tid >> 3;
    const int acol = (tid & 7) * 4;
    const int brow = tid >> 4;
    const int bcol = (tid & 15) * 4;
    float acc[4][4] = {};
    for (int k0 = 0; k0 < K; k0 += 32) {
#pragma unroll
        for (int rr = 0; rr < 2; rr++) {
            int r = arow + rr * 32;
            float4 v = *reinterpret_cast<const float4*>(&A[(size_t)(bm + r) * K + k0 + acol]);
            AsT[(acol + 0) * 68 + r] = v.x; AsT[(acol + 1) * 68 + r] = v.y;
            AsT[(acol + 2) * 68 + r] = v.z; AsT[(acol + 3) * 68 + r] = v.w;
        }
#pragma unroll
        for (int rr = 0; rr < 2; rr++) {
            float4 v = *reinterpret_cast<const float4*>(&B[(size_t)(k0 + brow + rr * 16) * N + bn + bcol]);
            *reinterpret_cast<float4*>(&Bs[(brow + rr * 16) * 68 + bcol]) = v;
        }
        __syncthreads();
#pragma unroll
        for (int kk = 0; kk < 32; kk++) {
            float4 a = *reinterpret_cast<const float4*>(&AsT[kk * 68 + r0]);
            float4 b = *reinterpret_cast<const float4*>(&Bs[kk * 68 + c0]);
            float av[4] = {a.x, a.y, a.z, a.w};
            float bv[4] = {b.x, b.y, b.z, b.w};
#pragma unroll
            for (int i = 0; i < 4; i++)
#pragma unroll
                for (int j = 0; j < 4; j++) acc[i][j] += av[i] * bv[j];
        }
        __syncthreads();
    }
    float4 bb = *reinterpret_cast<const float4*>(&bias[bn + c0]);
#pragma unroll
    for (int i = 0; i < 4; i++) {
        float4 o = make_float4(acc[i][0] + bb.x, acc[i][1] + bb.y, acc[i][2] + bb.z, acc[i][3] + bb.w);
        *reinterpret_cast<float4*>(&C[(size_t)(bm + r0 + i) * N + bn + c0]) = o;
    }
}

// ---------------- K2: M[n,q,kj] = sum_i qproj[q,i] * Wkq[n,kj,i] ----------------
__global__ __launch_bounds__(256) void compute_M_kernel(const float* __restrict__ Wkq) {
    __shared__ float AsT[64 * 68];   // [i][q]
    __shared__ float BsT[64 * 68];   // [i][kj]
    const int n = blockIdx.z;
    const int bq = blockIdx.y * 64;
    const int bkj = blockIdx.x * 64;
    const int tid = threadIdx.x;
    const int row = tid >> 4;
    const int col = (tid & 15) * 4;
#pragma unroll
    for (int rr = 0; rr < 4; rr++) {
        int r = row + rr * 16;
        float4 va = *reinterpret_cast<const float4*>(&g_proj[(size_t)(bq + r) * NPROJ + 1024 + n * 64 + col]);
        AsT[(col + 0) * 68 + r] = va.x; AsT[(col + 1) * 68 + r] = va.y;
        AsT[(col + 2) * 68 + r] = va.z; AsT[(col + 3) * 68 + r] = va.w;
        float4 vb = *reinterpret_cast<const float4*>(&Wkq[(size_t)n * 262144 + (size_t)(bkj + r) * 64 + col]);
        BsT[(col + 0) * 68 + r] = vb.x; BsT[(col + 1) * 68 + r] = vb.y;
        BsT[(col + 2) * 68 + r] = vb.z; BsT[(col + 3) * 68 + r] = vb.w;
    }
    __syncthreads();
    const int q0 = (tid & 15) * 4;
    const int kj0 = (tid >> 4) * 4;
    float acc[4][4] = {};
#pragma unroll 8
    for (int i = 0; i < 64; i++) {
        float4 a = *reinterpret_cast<const float4*>(&AsT[i * 68 + q0]);
        float4 b = *reinterpret_cast<const float4*>(&BsT[i * 68 + kj0]);
        float av[4] = {a.x, a.y, a.z, a.w};
        float bv[4] = {b.x, b.y, b.z, b.w};
#pragma unroll
        for (int ii = 0; ii < 4; ii++)
#pragma unroll
            for (int jj = 0; jj < 4; jj++) acc[ii][jj] += av[ii] * bv[jj];
    }
#pragma unroll
    for (int ii = 0; ii < 4; ii++) {
        float4 o = make_float4(acc[ii][0], acc[ii][1], acc[ii][2], acc[ii][3]);
        *reinterpret_cast<float4*>(&g_M[(size_t)(n * T_SEQ + bq + q0 + ii) * 4096 + bkj + kj0]) = o;
    }
}

// ---------------- K3: attention, 2 CTAs per (n,q) split by p-half ----------------
// smem regions (floats), total 24840 = 99360 B -> 2 CTAs/SM
// U   [0, 8448): phase1 k1T (stride 129, 64x128p); phase2 k2T (stride 68) + v2 at 4352; phase3 v1s (128x64)
// BT  [8448, 16640): [64j][128p]
// ET  [16640, 24832): [64t][128p]; M (stride 64, 4096) during phase 1; RT (c,p) phase 3
// red [24832, 24840)
#define OFF_U   0
#define OFF_V2U 4352
#define OFF_BT  8448
#define OFF_ET  16640
#define OFF_RED 24832
#define ATTN_SMEM_FLOATS 24840
#define ATTN_SMEM_BYTES (ATTN_SMEM_FLOATS * 4)

// NI = ceil(p_count/32) in 1..4
template <int NI>
__device__ __forceinline__ void attn_body(float* sm, int n, int q, int ph, int tid) {
    float* U   = sm + OFF_U;
    float* BT  = sm + OFF_BT;    // stride 128
    float* ET  = sm + OFF_ET;    // stride 128
    float* red = sm + OFF_RED;

    const int P = q + 1;
    const int p_base = ph << 7;
    const int p_count = min(P - p_base, 128);
    const int pl = tid & 31;          // lane -> local p base
    const int tg = tid >> 5;          // warp
    const int c8 = tg * 8;            // warp's 8-wide c/t/j slot

    // ---- load M into ET region (stride 64) ----
    {
        const float* Mg = g_M + (size_t)(n * T_SEQ + q) * 4096;
        float* Ms = ET;
#pragma unroll
        for (int r = 0; r < 4; r++) {
            int off = (tid + r * 256) * 4;
            *reinterpret_cast<float4*>(&Ms[off]) = *reinterpret_cast<const float4*>(&Mg[off]);
        }
    }
    // ---- load k1 transposed [k][local p] (stride 129), zero past p_count ----
    {
        float* k1T = U;
        const int rr = tid >> 4;            // 0..15
        const int iv = (tid & 15) * 4;
#pragma unroll
        for (int pass = 0; pass < NI * 2; pass++) {
            int lp = pass * 16 + rr;
            int gp = p_base + lp;
            float4 v = make_float4(0.f, 0.f, 0.f, 0.f);
            if (lp < p_count) v = *reinterpret_cast<const float4*>(&g_proj[(size_t)gp * NPROJ + n * 64 + iv]);
            k1T[(iv + 0) * 129 + lp] = v.x;
            k1T[(iv + 1) * 129 + lp] = v.y;
            k1T[(iv + 2) * 129 + lp] = v.z;
            k1T[(iv + 3) * 129 + lp] = v.w;
        }
    }
    __syncthreads();

    // ---- phase 1: B[p,j] = sum_k k1[p,k]*M[k,j]; store BT[j][p] ----
    {
        const float* k1T = U;
        const float* Ms = ET;
        float acc[NI][8];
#pragma unroll
        for (int i = 0; i < NI; i++)
#pragma unroll
            for (int j = 0; j < 8; j++) acc[i][j] = 0.f;
#pragma unroll 4
        for (int k = 0; k < 64; k++) {
            float a[NI];
#pragma unroll
            for (int i = 0; i < NI; i++) a[i] = k1T[k * 129 + pl + 32 * i];
            float4 b0 = *reinterpret_cast<const float4*>(&Ms[k * 64 + c8]);
            float4 b1 = *reinterpret_cast<const float4*>(&Ms[k * 64 + c8 + 4]);
            float b[8] = {b0.x, b0.y, b0.z, b0.w, b1.x, b1.y, b1.z, b1.w};
#pragma unroll
            for (int i = 0; i < NI; i++)
#pragma unroll
                for (int j = 0; j < 8; j++) acc[i][j] += a[i] * b[j];
        }
        __syncthreads();   // M (in ET) fully consumed before ET reused for E
#pragma unroll
        for (int j = 0; j < 8; j++)
#pragma unroll
            for (int i = 0; i < NI; i++)
                BT[(c8 + j) * 128 + pl + 32 * i] = acc[i][j];
    }
    __syncthreads();

    // ---- phase 2: stream t-tiles over full [0, P) ----
    float R[NI][8];
#pragma unroll
    for (int i = 0; i < NI; i++)
#pragma unroll
        for (int j = 0; j < 8; j++) R[i][j] = 0.f;
    float lsum = 0.f;
    float* k2T = U;              // stride 68
    float* v2s = U + OFF_V2U;    // stride 64
    for (int t0 = 0; t0 < P; t0 += 64) {
        {   // load k2 transposed [j][t] + v2 [t][c], zero past P
            const int rr = tid >> 4;
            const int iv = (tid & 15) * 4;
#pragma unroll
            for (int pass = 0; pass < 4; pass++) {
                int t = pass * 16 + rr;
                int gt = t0 + t;
                float4 a = make_float4(0.f, 0.f, 0.f, 0.f);
                float4 b = make_float4(0.f, 0.f, 0.f, 0.f);
                if (gt < P) {
                    a = *reinterpret_cast<const float4*>(&g_proj[(size_t)gt * NPROJ + 512 + n * 64 + iv]);
                    b = *reinterpret_cast<const float4*>(&g_proj[(size_t)gt * NPROJ + 2048 + n * 64 + iv]);
                }
                k2T[(iv + 0) * 68 + t] = a.x;
                k2T[(iv + 1) * 68 + t] = a.y;
                k2T[(iv + 2) * 68 + t] = a.z;
                k2T[(iv + 3) * 68 + t] = a.w;
                *reinterpret_cast<float4*>(&v2s[t * 64 + iv]) = b;
            }
        }
        __syncthreads();
        // ---- S + exp + store ET[t][p] ----
        {
            float s[NI][8];
#pragma unroll
            for (int i = 0; i < NI; i++)
#pragma unroll
                for (int j = 0; j < 8; j++) s[i][j] = 0.f;
#pragma unroll 4
            for (int j = 0; j < 64; j++) {
                float a[NI];
#pragma unroll
                for (int i = 0; i < NI; i++) a[i] = BT[j * 128 + pl + 32 * i];
                float4 b0 = *reinterpret_cast<const float4*>(&k2T[j * 68 + c8]);
                float4 b1 = *reinterpret_cast<const float4*>(&k2T[j * 68 + c8 + 4]);
                float b[8] = {b0.x, b0.y, b0.z, b0.w, b1.x, b1.y, b1.z, b1.w};
#pragma unroll
                for (int i = 0; i < NI; i++)
#pragma unroll
                    for (int jj = 0; jj < 8; jj++) s[i][jj] += a[i] * b[jj];
            }
#pragma unroll
            for (int i = 0; i < NI; i++) {
                int gp = p_base + pl + 32 * i;
#pragma unroll
                for (int jj = 0; jj < 8; jj++) {
                    int t = t0 + c8 + jj;
                    float e = (gp < P && t < P) ? __expf(s[i][jj] * 0.015625f) : 0.f;
                    lsum += e;
                    ET[(c8 + jj) * 128 + pl + 32 * i] = e;
                }
            }
        }
        __syncthreads();
        // ---- R[p,c] += sum_t E[p,t] * v2[t,c] ----
#pragma unroll 4
        for (int t = 0; t < 64; t++) {
            float a[NI];
#pragma unroll
            for (int i = 0; i < NI; i++) a[i] = ET[t * 128 + pl + 32 * i];
            float4 b0 = *reinterpret_cast<const float4*>(&v2s[t * 64 + c8]);
            float4 b1 = *reinterpret_cast<const float4*>(&v2s[t * 64 + c8 + 4]);
            float b[8] = {b0.x, b0.y, b0.z, b0.w, b1.x, b1.y, b1.z, b1.w};
#pragma unroll
            for (int i = 0; i < NI; i++)
#pragma unroll
                for (int j = 0; j < 8; j++) R[i][j] += a[i] * b[j];
        }
        __syncthreads();
    }

    // ---- stage RT[c][local p] into ET; load v1 rows into U ----
#pragma unroll
    for (int j = 0; j < 8; j++)
#pragma unroll
        for (int i = 0; i < NI; i++)
            ET[(c8 + j) * 128 + pl + 32 * i] = R[i][j];
    {
        float* v1s = U;   // [128][64]; rows >= p_count never read
        const int rr = tid >> 4;
        const int iv = (tid & 15) * 4;
#pragma unroll
        for (int pass = 0; pass < NI * 2; pass++) {
            int lp = pass * 16 + rr;
            if (lp < p_count) {
                float4 v = *reinterpret_cast<const float4*>(
                    &g_proj[(size_t)(p_base + lp) * NPROJ + 1536 + n * 64 + iv]);
                *reinterpret_cast<float4*>(&v1s[lp * 64 + iv]) = v;
            }
        }
    }
    // lsum reduce -> partial slot
#pragma unroll
    for (int off = 16; off > 0; off >>= 1)
        lsum += __shfl_xor_sync(0xffffffffu, lsum, off);
    if (pl == 0) red[tg] = lsum;
    __syncthreads();
    if (tid == 0) {
        float total = 0.f;
#pragma unroll
        for (int w = 0; w < 8; w++) total += red[w];
        g_l[ph * (NH * T_SEQ) + n * T_SEQ + q] = total;
    }

    // ---- phase 3: G[a,c] = sum_{lp<p_count} v1[lp,a] * RT[c,lp] ----
    {
        const float* v1s = U;
        const float* RT = ET;
        const int a0 = (tid & 15) * 4;
        const int c0 = (tid >> 4) * 4;
        float acc[4][4] = {};
#pragma unroll 4
        for (int p = 0; p < p_count; p++) {
            float4 av = *reinterpret_cast<const float4*>(&v1s[p * 64 + a0]);
            float avv[4] = {av.x, av.y, av.z, av.w};
            float rv[4];
#pragma unroll
            for (int k = 0; k < 4; k++) rv[k] = RT[(c0 + k) * 128 + p];
#pragma unroll
            for (int ka = 0; ka < 4; ka++)
#pragma unroll
                for (int kc = 0; kc < 4; kc++) acc[ka][kc] += avv[ka] * rv[kc];
        }
        float* Gout = (ph ? g_Gb : g_Ga) + (size_t)(n * T_SEQ + q) * 4096;
#pragma unroll
        for (int ka = 0; ka < 4; ka++) {
            float4 o = make_float4(acc[ka][0], acc[ka][1], acc[ka][2], acc[ka][3]);
            *reinterpret_cast<float4*>(&Gout[(a0 + ka) * 64 + c0]) = o;
        }
    }
}

__global__ __launch_bounds__(256, 2) void attn_kernel() {
    extern __shared__ float sm[];
    const int bid = blockIdx.x;
    const int q = 255 - (bid >> 4);       // big-q first
    const int n = (bid >> 1) & 7;
    const int ph = bid & 1;
    const int P = q + 1;
    const int p_count = P - (ph << 7);
    if (p_count <= 0) return;             // no second half for q < 128
    const int ni = (min(p_count, 128) + 31) >> 5;
    switch (ni) {
        case 1: attn_body<1>(sm, n, q, ph, threadIdx.x); break;
        case 2: attn_body<2>(sm, n, q, ph, threadIdx.x); break;
        case 3: attn_body<3>(sm, n, q, ph, threadIdx.x); break;
        default: attn_body<4>(sm, n, q, ph, threadIdx.x); break;
    }
}

// ---------------- K4: z_raw += (Ga+Gb) @ W_Vq (K-split, atomics) ----------------
__global__ __launch_bounds__(256) void out_v_kernel(const float* __restrict__ Wvq) {
    __shared__ float AsT[32 * 68];  // [k][q]
    __shared__ float Bs[32 * 68];   // [k][e]
    const int n = blockIdx.y;
    const int bq = blockIdx.x * 64;
    const int ks = blockIdx.z;
    const int tid = threadIdx.x;
    const bool two = (bq >= 128);   // q >= 128 rows have a second G half
    const int arow = tid >> 3, acol = (tid & 7) * 4;
    const int brow = tid >> 4, bcol = (tid & 15) * 4;
    const int q0 = (tid & 15) * 4, e0 = (tid >> 4) * 4;
    float acc[4][4] = {};
    for (int k0 = ks * 1024; k0 < ks * 1024 + 1024; k0 += 32) {
#pragma unroll
        for (int rr = 0; rr < 2; rr++) {
            int r = arow + rr * 32;
            size_t idx = (size_t)(n * T_SEQ + bq + r) * 4096 + k0 + acol;
            float4 v = *reinterpret_cast<const float4*>(&g_Ga[idx]);
            if (two) {
                float4 w = *reinterpret_cast<const float4*>(&g_Gb[idx]);
                v.x += w.x; v.y += w.y; v.z += w.z; v.w += w.w;
            }
            AsT[(acol + 0) * 68 + r] = v.x; AsT[(acol + 1) * 68 + r] = v.y;
            AsT[(acol + 2) * 68 + r] = v.z; AsT[(acol + 3) * 68 + r] = v.w;
        }
#pragma unroll
        for (int rr = 0; rr < 2; rr++) {
            float4 v = *reinterpret_cast<const float4*>(
                &Wvq[(size_t)n * 262144 + (size_t)(k0 + brow + rr * 16) * 64 + bcol]);
            *reinterpret_cast<float4*>(&Bs[(brow + rr * 16) * 68 + bcol]) = v;
        }
        __syncthreads();
#pragma unroll
        for (int kk = 0; kk < 32; kk++) {
            float4 a = *reinterpret_cast<const float4*>(&AsT[kk * 68 + q0]);
            float4 b = *reinterpret_cast<const float4*>(&Bs[kk * 68 + e0]);
            float av[4] = {a.x, a.y, a.z, a.w};
            float bv[4] = {b.x, b.y, b.z, b.w};
#pragma unroll
            for (int i = 0; i < 4; i++)
#pragma unroll
                for (int j = 0; j < 4; j++) acc[i][j] += av[i] * bv[j];
        }
        __syncthreads();
    }
#pragma unroll
    for (int i = 0; i < 4; i++)
#pragma unroll
        for (int j = 0; j < 4; j++)
            atomicAdd(&g_z[(size_t)(bq + q0 + i) * DMODEL + n * 64 + e0 + j], acc[i][j]);
}

// ---------------- K5: out = (z_raw * 1/(la+lb)) @ W_out + b_out ----------------
__global__ __launch_bounds__(256) void gemm_out_kernel(
    const float* __restrict__ Wout, const float* __restrict__ bout, float* __restrict__ C) {
    __shared__ float AsT[32 * 68];  // [k][m]
    __shared__ float Bs[32 * 68];   // [k][n]
    const int tid = threadIdx.x;
    const int bm = blockIdx.y * 64;
    const int bn = blockIdx.x * 64;
    const int r0 = (tid & 15) * 4;
    const int c0 = (tid >> 4) * 4;
    const int arow = tid >> 3, acol = (tid & 7) * 4;
    const int brow = tid >> 4, bcol = (tid & 15) * 4;
    float acc[4][4] = {};
    for (int k0 = 0; k0 < DMODEL; k0 += 32) {
#pragma unroll
        for (int rr = 0; rr < 2; rr++) {
            int r = bm + arow + rr * 32;
            int gk = k0 + acol;
            int li = (gk >> 6) * T_SEQ + r;
            float invl = 1.f / (g_l[li] + g_l[NH * T_SEQ + li]);
            float4 v = *reinterpret_cast<const float4*>(&g_z[(size_t)r * DMODEL + gk]);
            AsT[(acol + 0) * 68 + arow + rr * 32] = v.x * invl;
            AsT[(acol + 1) * 68 + arow + rr * 32] = v.y * invl;
            AsT[(acol + 2) * 68 + arow + rr * 32] = v.z * invl;
            AsT[(acol + 3) * 68 + arow + rr * 32] = v.w * invl;
        }
#pragma unroll
        for (int rr = 0; rr < 2; rr++) {
            float4 v = *reinterpret_cast<const float4*>(&Wout[(size_t)(k0 + brow + rr * 16) * DMODEL + bn + bcol]);
            *reinterpret_cast<float4*>(&Bs[(brow + rr * 16) * 68 + bcol]) = v;
        }
        __syncthreads();
#pragma unroll
        for (int kk = 0; kk < 32; kk++) {
            float4 a = *reinterpret_cast<const float4*>(&AsT[kk * 68 + r0]);
            float4 b = *reinterpret_cast<const float4*>(&Bs[kk * 68 + c0]);
            float av[4] = {a.x, a.y, a.z, a.w};
            float bv[4] = {b.x, b.y, b.z, b.w};
#pragma unroll
            for (int i = 0; i < 4; i++)
#pragma unroll
                for (int j = 0; j < 4; j++) acc[i][j] += av[i] * bv[j];
        }
        __syncthreads();
    }
    float4 bb = *reinterpret_cast<const float4*>(&bout[bn + c0]);
#pragma unroll
    for (int i = 0; i < 4; i++) {
        float4 o = make_float4(acc[i][0] + bb.x, acc[i][1] + bb.y, acc[i][2] + bb.z, acc[i][3] + bb.w);
        *reinterpret_cast<float4*>(&C[(size_t)(bm + r0 + i) * DMODEL + bn + c0]) = o;
    }
}

// ---------------- launch ----------------
extern "C" void kernel_launch(void* const* d_in, const int* in_sizes, int n_in,
                              void* d_out, int out_size) {
    const float* x       = (const float*)d_in[0];
    const float* Wkkqvv  = (const float*)d_in[1];
    const float* bkkqvv  = (const float*)d_in[2];
    const float* WKq     = (const float*)d_in[3];
    const float* WVq     = (const float*)d_in[4];
    const float* Wout    = (const float*)d_in[5];
    const float* bout    = (const float*)d_in[6];
    float* out = (float*)d_out;

    float* proj_ptr = nullptr;
    cudaGetSymbolAddress((void**)&proj_ptr, g_proj);

    cudaFuncSetAttribute(attn_kernel, cudaFuncAttributeMaxDynamicSharedMemorySize, ATTN_SMEM_BYTES);

    zero_kernel<<<(NZERO + 255) / 256, 256>>>();
    gemm_nn_bias_kernel<<<dim3(NPROJ / 64, T_SEQ / 64), 256>>>(x, Wkkqvv, bkkqvv, proj_ptr,
                                                               T_SEQ, NPROJ, DMODEL);
    compute_M_kernel<<<dim3(64, 4, NH), 256>>>(WKq);
    attn_kernel<<<NH * T_SEQ * 2, 256, ATTN_SMEM_BYTES>>>();
    out_v_kernel<<<dim3(4, NH, 4), 256>>>(WVq);
    gemm_out_kernel<<<dim3(DMODEL / 64, T_SEQ / 64), 256>>>(Wout, bout, out);
}

// round 8
// speedup vs baseline: 1.2486x; 1.0884x over previous
#include <cuda_runtime.h>

#define T_SEQ 256
#define NH 8
#define DHD 64
#define DMODEL 512
#define NPROJ 2560   // 5 * 512

// ---------------- packed fp32x2 helpers (Blackwell FFMA2) ----------------
__device__ __forceinline__ unsigned long long splat2(float x) {
    unsigned long long r;
    asm("mov.b64 %0, {%1, %1};" : "=l"(r) : "f"(x));
    return r;
}
__device__ __forceinline__ unsigned long long fma2(unsigned long long a, unsigned long long b,
                                                   unsigned long long c) {
    unsigned long long d;
    asm("fma.rn.f32x2 %0, %1, %2, %3;" : "=l"(d) : "l"(a), "l"(b), "l"(c));
    return d;
}
__device__ __forceinline__ float2 unpack2(unsigned long long v) {
    float2 f;
    asm("mov.b64 {%0, %1}, %2;" : "=f"(f.x), "=f"(f.y) : "l"(v));
    return f;
}

// ---------------- scratch ----------------
__device__ float g_proj[T_SEQ * NPROJ];            // [t, 2560]
__device__ float g_M[NH * T_SEQ * DHD * DHD];      // [n, q, k, j]
__device__ float g_Ga[NH * T_SEQ * DHD * DHD];     // [n, q, a, c] p-half 0
__device__ float g_Gb[NH * T_SEQ * DHD * DHD];     // [n, q, a, c] p-half 1
__device__ float g_l[2 * NH * T_SEQ];              // softmax denominator partials
__device__ float g_z[T_SEQ * DMODEL];              // [q, n*64+e] (unnormalized accum)

// ---------------- K0: zero z + l ----------------
#define NZERO (T_SEQ * DMODEL + 2 * NH * T_SEQ)
__global__ __launch_bounds__(256) void zero_kernel() {
    int i = blockIdx.x * 256 + threadIdx.x;
    if (i < T_SEQ * DMODEL) g_z[i] = 0.f;
    else g_l[i - T_SEQ * DMODEL] = 0.f;
}

// ---------------- K1: C[M,N] = A[M,K] @ B[K,N] + bias ----------------
__global__ __launch_bounds__(256) void gemm_nn_bias_kernel(
    const float* __restrict__ A, const float* __restrict__ B,
    const float* __restrict__ bias, float* __restrict__ C,
    int M, int N, int K) {
    __shared__ float AsT[32 * 68];   // [k][m]
    __shared__ float Bs[32 * 68];    // [k][n]
    const int tid = threadIdx.x;
    const int bm = blockIdx.y * 64;
    const int bn = blockIdx.x * 64;
    const int r0 = (tid & 15) * 4;
    const int c0 = (tid >> 4) * 4;
    const int arow = tid >> 3;
    const int acol = (tid & 7) * 4;
    const int brow = tid >> 4;
    const int bcol = (tid & 15) * 4;
    unsigned long long acc2[4][2] = {};
    for (int k0 = 0; k0 < K; k0 += 32) {
#pragma unroll
        for (int rr = 0; rr < 2; rr++) {
            int r = arow + rr * 32;
            float4 v = *reinterpret_cast<const float4*>(&A[(size_t)(bm + r) * K + k0 + acol]);
            AsT[(acol + 0) * 68 + r] = v.x; AsT[(acol + 1) * 68 + r] = v.y;
            AsT[(acol + 2) * 68 + r] = v.z; AsT[(acol + 3) * 68 + r] = v.w;
        }
#pragma unroll
        for (int rr = 0; rr < 2; rr++) {
            float4 v = *reinterpret_cast<const float4*>(&B[(size_t)(k0 + brow + rr * 16) * N + bn + bcol]);
            *reinterpret_cast<float4*>(&Bs[(brow + rr * 16) * 68 + bcol]) = v;
        }
        __syncthreads();
#pragma unroll
        for (int kk = 0; kk < 32; kk++) {
            float4 a = *reinterpret_cast<const float4*>(&AsT[kk * 68 + r0]);
            ulonglong2 b2 = *reinterpret_cast<const ulonglong2*>(&Bs[kk * 68 + c0]);
            unsigned long long as[4] = {splat2(a.x), splat2(a.y), splat2(a.z), splat2(a.w)};
#pragma unroll
            for (int i = 0; i < 4; i++) {
                acc2[i][0] = fma2(as[i], b2.x, acc2[i][0]);
                acc2[i][1] = fma2(as[i], b2.y, acc2[i][1]);
            }
        }
        __syncthreads();
    }
    float4 bb = *reinterpret_cast<const float4*>(&bias[bn + c0]);
#pragma unroll
    for (int i = 0; i < 4; i++) {
        float2 p0 = unpack2(acc2[i][0]);
        float2 p1 = unpack2(acc2[i][1]);
        float4 o = make_float4(p0.x + bb.x, p0.y + bb.y, p1.x + bb.z, p1.y + bb.w);
        *reinterpret_cast<float4*>(&C[(size_t)(bm + r0 + i) * N + bn + c0]) = o;
    }
}

// ---------------- K2: M[n,q,kj] = sum_i qproj[q,i] * Wkq[n,kj,i] ----------------
__global__ __launch_bounds__(256) void compute_M_kernel(const float* __restrict__ Wkq) {
    __shared__ float AsT[64 * 68];   // [i][q]
    __shared__ float BsT[64 * 68];   // [i][kj]
    const int n = blockIdx.z;
    const int bq = blockIdx.y * 64;
    const int bkj = blockIdx.x * 64;
    const int tid = threadIdx.x;
    const int row = tid >> 4;
    const int col = (tid & 15) * 4;
#pragma unroll
    for (int rr = 0; rr < 4; rr++) {
        int r = row + rr * 16;
        float4 va = *reinterpret_cast<const float4*>(&g_proj[(size_t)(bq + r) * NPROJ + 1024 + n * 64 + col]);
        AsT[(col + 0) * 68 + r] = va.x; AsT[(col + 1) * 68 + r] = va.y;
        AsT[(col + 2) * 68 + r] = va.z; AsT[(col + 3) * 68 + r] = va.w;
        float4 vb = *reinterpret_cast<const float4*>(&Wkq[(size_t)n * 262144 + (size_t)(bkj + r) * 64 + col]);
        BsT[(col + 0) * 68 + r] = vb.x; BsT[(col + 1) * 68 + r] = vb.y;
        BsT[(col + 2) * 68 + r] = vb.z; BsT[(col + 3) * 68 + r] = vb.w;
    }
    __syncthreads();
    const int q0 = (tid & 15) * 4;
    const int kj0 = (tid >> 4) * 4;
    unsigned long long acc2[4][2] = {};
#pragma unroll 8
    for (int i = 0; i < 64; i++) {
        float4 a = *reinterpret_cast<const float4*>(&AsT[i * 68 + q0]);
        ulonglong2 b2 = *reinterpret_cast<const ulonglong2*>(&BsT[i * 68 + kj0]);
        unsigned long long as[4] = {splat2(a.x), splat2(a.y), splat2(a.z), splat2(a.w)};
#pragma unroll
        for (int ii = 0; ii < 4; ii++) {
            acc2[ii][0] = fma2(as[ii], b2.x, acc2[ii][0]);
            acc2[ii][1] = fma2(as[ii], b2.y, acc2[ii][1]);
        }
    }
#pragma unroll
    for (int ii = 0; ii < 4; ii++) {
        float2 p0 = unpack2(acc2[ii][0]);
        float2 p1 = unpack2(acc2[ii][1]);
        float4 o = make_float4(p0.x, p0.y, p1.x, p1.y);
        *reinterpret_cast<float4*>(&g_M[(size_t)(n * T_SEQ + bq + q0 + ii) * 4096 + bkj + kj0]) = o;
    }
}

// ---------------- K3: attention, 2 CTAs per (n,q) split by p-half ----------------
#define OFF_U   0
#define OFF_V2U 4352
#define OFF_BT  8448
#define OFF_ET  16640
#define OFF_RED 24832
#define ATTN_SMEM_FLOATS 24840
#define ATTN_SMEM_BYTES (ATTN_SMEM_FLOATS * 4)

// NI = ceil(p_count/32) in 1..4
template <int NI>
__device__ __forceinline__ void attn_body(float* sm, int n, int q, int ph, int tid) {
    float* U   = sm + OFF_U;
    float* BT  = sm + OFF_BT;    // stride 128
    float* ET  = sm + OFF_ET;    // stride 128
    float* red = sm + OFF_RED;

    const int P = q + 1;
    const int p_base = ph << 7;
    const int p_count = min(P - p_base, 128);
    const int pl = tid & 31;
    const int tg = tid >> 5;
    const int c8 = tg * 8;

    // ---- load M into ET region (stride 64) ----
    {
        const float* Mg = g_M + (size_t)(n * T_SEQ + q) * 4096;
        float* Ms = ET;
#pragma unroll
        for (int r = 0; r < 4; r++) {
            int off = (tid + r * 256) * 4;
            *reinterpret_cast<float4*>(&Ms[off]) = *reinterpret_cast<const float4*>(&Mg[off]);
        }
    }
    // ---- load k1 transposed [k][local p] (stride 129) ----
    {
        float* k1T = U;
        const int rr = tid >> 4;
        const int iv = (tid & 15) * 4;
#pragma unroll
        for (int pass = 0; pass < NI * 2; pass++) {
            int lp = pass * 16 + rr;
            int gp = p_base + lp;
            float4 v = make_float4(0.f, 0.f, 0.f, 0.f);
            if (lp < p_count) v = *reinterpret_cast<const float4*>(&g_proj[(size_t)gp * NPROJ + n * 64 + iv]);
            k1T[(iv + 0) * 129 + lp] = v.x;
            k1T[(iv + 1) * 129 + lp] = v.y;
            k1T[(iv + 2) * 129 + lp] = v.z;
            k1T[(iv + 3) * 129 + lp] = v.w;
        }
    }
    __syncthreads();

    // ---- phase 1: B[p,j] = sum_k k1[p,k]*M[k,j]; store BT[j][p] ----
    {
        const float* k1T = U;
        const float* Ms = ET;
        unsigned long long acc2[NI][4] = {};
#pragma unroll 4
        for (int k = 0; k < 64; k++) {
            unsigned long long a2[NI];
#pragma unroll
            for (int i = 0; i < NI; i++) a2[i] = splat2(k1T[k * 129 + pl + 32 * i]);
            const ulonglong2* bp = reinterpret_cast<const ulonglong2*>(&Ms[k * 64 + c8]);
            ulonglong2 b01 = bp[0], b23 = bp[1];
#pragma unroll
            for (int i = 0; i < NI; i++) {
                acc2[i][0] = fma2(a2[i], b01.x, acc2[i][0]);
                acc2[i][1] = fma2(a2[i], b01.y, acc2[i][1]);
                acc2[i][2] = fma2(a2[i], b23.x, acc2[i][2]);
                acc2[i][3] = fma2(a2[i], b23.y, acc2[i][3]);
            }
        }
        __syncthreads();   // M (in ET) consumed
#pragma unroll
        for (int m = 0; m < 4; m++)
#pragma unroll
            for (int i = 0; i < NI; i++) {
                float2 v = unpack2(acc2[i][m]);
                BT[(c8 + 2 * m + 0) * 128 + pl + 32 * i] = v.x;
                BT[(c8 + 2 * m + 1) * 128 + pl + 32 * i] = v.y;
            }
    }
    __syncthreads();

    // ---- phase 2: stream t-tiles over [0, P) ----
    unsigned long long R2[NI][4] = {};
    float lsum = 0.f;
    float* k2T = U;              // stride 68
    float* v2s = U + OFF_V2U;    // stride 64
    for (int t0 = 0; t0 < P; t0 += 64) {
        {   // load k2 transposed [j][t] + v2 [t][c], zero past P
            const int rr = tid >> 4;
            const int iv = (tid & 15) * 4;
#pragma unroll
            for (int pass = 0; pass < 4; pass++) {
                int t = pass * 16 + rr;
                int gt = t0 + t;
                float4 a = make_float4(0.f, 0.f, 0.f, 0.f);
                float4 b = make_float4(0.f, 0.f, 0.f, 0.f);
                if (gt < P) {
                    a = *reinterpret_cast<const float4*>(&g_proj[(size_t)gt * NPROJ + 512 + n * 64 + iv]);
                    b = *reinterpret_cast<const float4*>(&g_proj[(size_t)gt * NPROJ + 2048 + n * 64 + iv]);
                }
                k2T[(iv + 0) * 68 + t] = a.x;
                k2T[(iv + 1) * 68 + t] = a.y;
                k2T[(iv + 2) * 68 + t] = a.z;
                k2T[(iv + 3) * 68 + t] = a.w;
                *reinterpret_cast<float4*>(&v2s[t * 64 + iv]) = b;
            }
        }
        __syncthreads();
        // ---- S + exp + store ET[t][p] ----
        {
            unsigned long long s2[NI][4] = {};
#pragma unroll 4
            for (int j = 0; j < 64; j++) {
                unsigned long long a2[NI];
#pragma unroll
                for (int i = 0; i < NI; i++) a2[i] = splat2(BT[j * 128 + pl + 32 * i]);
                const ulonglong2* bp = reinterpret_cast<const ulonglong2*>(&k2T[j * 68 + c8]);
                ulonglong2 b01 = bp[0], b23 = bp[1];
#pragma unroll
                for (int i = 0; i < NI; i++) {
                    s2[i][0] = fma2(a2[i], b01.x, s2[i][0]);
                    s2[i][1] = fma2(a2[i], b01.y, s2[i][1]);
                    s2[i][2] = fma2(a2[i], b23.x, s2[i][2]);
                    s2[i][3] = fma2(a2[i], b23.y, s2[i][3]);
                }
            }
#pragma unroll
            for (int i = 0; i < NI; i++) {
                int gp = p_base + pl + 32 * i;
#pragma unroll
                for (int m = 0; m < 4; m++) {
                    float2 sv = unpack2(s2[i][m]);
                    int t_lo = t0 + c8 + 2 * m;
                    float e_lo = (gp < P && t_lo < P) ? __expf(sv.x * 0.015625f) : 0.f;
                    float e_hi = (gp < P && t_lo + 1 < P) ? __expf(sv.y * 0.015625f) : 0.f;
                    lsum += e_lo + e_hi;
                    ET[(c8 + 2 * m + 0) * 128 + pl + 32 * i] = e_lo;
                    ET[(c8 + 2 * m + 1) * 128 + pl + 32 * i] = e_hi;
                }
            }
        }
        __syncthreads();
        // ---- R[p,c] += sum_t E[p,t] * v2[t,c] ----
#pragma unroll 4
        for (int t = 0; t < 64; t++) {
            unsigned long long a2[NI];
#pragma unroll
            for (int i = 0; i < NI; i++) a2[i] = splat2(ET[t * 128 + pl + 32 * i]);
            const ulonglong2* bp = reinterpret_cast<const ulonglong2*>(&v2s[t * 64 + c8]);
            ulonglong2 b01 = bp[0], b23 = bp[1];
#pragma unroll
            for (int i = 0; i < NI; i++) {
                R2[i][0] = fma2(a2[i], b01.x, R2[i][0]);
                R2[i][1] = fma2(a2[i], b01.y, R2[i][1]);
                R2[i][2] = fma2(a2[i], b23.x, R2[i][2]);
                R2[i][3] = fma2(a2[i], b23.y, R2[i][3]);
            }
        }
        __syncthreads();
    }

    // ---- stage RT[c][local p] into ET; load v1 rows into U ----
#pragma unroll
    for (int m = 0; m < 4; m++)
#pragma unroll
        for (int i = 0; i < NI; i++) {
            float2 v = unpack2(R2[i][m]);
            ET[(c8 + 2 * m + 0) * 128 + pl + 32 * i] = v.x;
            ET[(c8 + 2 * m + 1) * 128 + pl + 32 * i] = v.y;
        }
    {
        float* v1s = U;   // [128][64]
        const int rr = tid >> 4;
        const int iv = (tid & 15) * 4;
#pragma unroll
        for (int pass = 0; pass < NI * 2; pass++) {
            int lp = pass * 16 + rr;
            if (lp < p_count) {
                float4 v = *reinterpret_cast<const float4*>(
                    &g_proj[(size_t)(p_base + lp) * NPROJ + 1536 + n * 64 + iv]);
                *reinterpret_cast<float4*>(&v1s[lp * 64 + iv]) = v;
            }
        }
    }
    // lsum reduce
#pragma unroll
    for (int off = 16; off > 0; off >>= 1)
        lsum += __shfl_xor_sync(0xffffffffu, lsum, off);
    if (pl == 0) red[tg] = lsum;
    __syncthreads();
    if (tid == 0) {
        float total = 0.f;
#pragma unroll
        for (int w = 0; w < 8; w++) total += red[w];
        g_l[ph * (NH * T_SEQ) + n * T_SEQ + q] = total;
    }

    // ---- phase 3: G[a,c] = sum_{lp<p_count} v1[lp,a] * RT[c,lp], packed along a ----
    {
        const float* v1s = U;
        const float* RT = ET;
        const int a0 = (tid & 15) * 4;
        const int c0 = (tid >> 4) * 4;
        unsigned long long acc2[2][4] = {};
#pragma unroll 4
        for (int p = 0; p < p_count; p++) {
            ulonglong2 av2 = *reinterpret_cast<const ulonglong2*>(&v1s[p * 64 + a0]);
#pragma unroll
            for (int k = 0; k < 4; k++) {
                unsigned long long r2 = splat2(RT[(c0 + k) * 128 + p]);
                acc2[0][k] = fma2(av2.x, r2, acc2[0][k]);
                acc2[1][k] = fma2(av2.y, r2, acc2[1][k]);
            }
        }
        float* Gout = (ph ? g_Gb : g_Ga) + (size_t)(n * T_SEQ + q) * 4096;
#pragma unroll
        for (int h = 0; h < 2; h++) {
            float2 v0 = unpack2(acc2[h][0]);
            float2 v1 = unpack2(acc2[h][1]);
            float2 v2 = unpack2(acc2[h][2]);
            float2 v3 = unpack2(acc2[h][3]);
            float4 lo = make_float4(v0.x, v1.x, v2.x, v3.x);   // a = a0 + 2h
            float4 hi = make_float4(v0.y, v1.y, v2.y, v3.y);   // a = a0 + 2h + 1
            *reinterpret_cast<float4*>(&Gout[(a0 + 2 * h + 0) * 64 + c0]) = lo;
            *reinterpret_cast<float4*>(&Gout[(a0 + 2 * h + 1) * 64 + c0]) = hi;
        }
    }
}

__global__ __launch_bounds__(256, 2) void attn_kernel() {
    extern __shared__ float sm[];
    const int bid = blockIdx.x;
    const int q = 255 - (bid >> 4);
    const int n = (bid >> 1) & 7;
    const int ph = bid & 1;
    const int P = q + 1;
    const int p_count = P - (ph << 7);
    if (p_count <= 0) return;
    const int ni = (min(p_count, 128) + 31) >> 5;
    switch (ni) {
        case 1: attn_body<1>(sm, n, q, ph, threadIdx.x); break;
        case 2: attn_body<2>(sm, n, q, ph, threadIdx.x); break;
        case 3: attn_body<3>(sm, n, q, ph, threadIdx.x); break;
        default: attn_body<4>(sm, n, q, ph, threadIdx.x); break;
    }
}

// ---------------- K4: z_raw += (Ga+Gb) @ W_Vq (K-split, atomics) ----------------
__global__ __launch_bounds__(256) void out_v_kernel(const float* __restrict__ Wvq) {
    __shared__ float AsT[32 * 68];  // [k][q]
    __shared__ float Bs[32 * 68];   // [k][e]
    const int n = blockIdx.y;
    const int bq = blockIdx.x * 64;
    const int ks = blockIdx.z;
    const int tid = threadIdx.x;
    const bool two = (bq >= 128);
    const int arow = tid >> 3, acol = (tid & 7) * 4;
    const int brow = tid >> 4, bcol = (tid & 15) * 4;
    const int q0 = (tid & 15) * 4, e0 = (tid >> 4) * 4;
    unsigned long long acc2[4][2] = {};
    for (int k0 = ks * 1024; k0 < ks * 1024 + 1024; k0 += 32) {
#pragma unroll
        for (int rr = 0; rr < 2; rr++) {
            int r = arow + rr * 32;
            size_t idx = (size_t)(n * T_SEQ + bq + r) * 4096 + k0 + acol;
            float4 v = *reinterpret_cast<const float4*>(&g_Ga[idx]);
            if (two) {
                float4 w = *reinterpret_cast<const float4*>(&g_Gb[idx]);
                v.x += w.x; v.y += w.y; v.z += w.z; v.w += w.w;
            }
            AsT[(acol + 0) * 68 + r] = v.x; AsT[(acol + 1) * 68 + r] = v.y;
            AsT[(acol + 2) * 68 + r] = v.z; AsT[(acol + 3) * 68 + r] = v.w;
        }
#pragma unroll
        for (int rr = 0; rr < 2; rr++) {
            float4 v = *reinterpret_cast<const float4*>(
                &Wvq[(size_t)n * 262144 + (size_t)(k0 + brow + rr * 16) * 64 + bcol]);
            *reinterpret_cast<float4*>(&Bs[(brow + rr * 16) * 68 + bcol]) = v;
        }
        __syncthreads();
#pragma unroll
        for (int kk = 0; kk < 32; kk++) {
            float4 a = *reinterpret_cast<const float4*>(&AsT[kk * 68 + q0]);
            ulonglong2 b2 = *reinterpret_cast<const ulonglong2*>(&Bs[kk * 68 + e0]);
            unsigned long long as[4] = {splat2(a.x), splat2(a.y), splat2(a.z), splat2(a.w)};
#pragma unroll
            for (int i = 0; i < 4; i++) {
                acc2[i][0] = fma2(as[i], b2.x, acc2[i][0]);
                acc2[i][1] = fma2(as[i], b2.y, acc2[i][1]);
            }
        }
        __syncthreads();
    }
#pragma unroll
    for (int i = 0; i < 4; i++) {
        float2 p0 = unpack2(acc2[i][0]);
        float2 p1 = unpack2(acc2[i][1]);
        float* zp = &g_z[(size_t)(bq + q0 + i) * DMODEL + n * 64 + e0];
        atomicAdd(zp + 0, p0.x);
        atomicAdd(zp + 1, p0.y);
        atomicAdd(zp + 2, p1.x);
        atomicAdd(zp + 3, p1.y);
    }
}

// ---------------- K5: out = (z_raw * 1/(la+lb)) @ W_out + b_out ----------------
__global__ __launch_bounds__(256) void gemm_out_kernel(
    const float* __restrict__ Wout, const float* __restrict__ bout, float* __restrict__ C) {
    __shared__ float AsT[32 * 68];  // [k][m]
    __shared__ float Bs[32 * 68];   // [k][n]
    const int tid = threadIdx.x;
    const int bm = blockIdx.y * 64;
    const int bn = blockIdx.x * 64;
    const int r0 = (tid & 15) * 4;
    const int c0 = (tid >> 4) * 4;
    const int arow = tid >> 3, acol = (tid & 7) * 4;
    const int brow = tid >> 4, bcol = (tid & 15) * 4;
    unsigned long long acc2[4][2] = {};
    for (int k0 = 0; k0 < DMODEL; k0 += 32) {
#pragma unroll
        for (int rr = 0; rr < 2; rr++) {
            int r = bm + arow + rr * 32;
            int gk = k0 + acol;
            int li = (gk >> 6) * T_SEQ + r;
            float invl = 1.f / (g_l[li] + g_l[NH * T_SEQ + li]);
            float4 v = *reinterpret_cast<const float4*>(&g_z[(size_t)r * DMODEL + gk]);
            AsT[(acol + 0) * 68 + arow + rr * 32] = v.x * invl;
            AsT[(acol + 1) * 68 + arow + rr * 32] = v.y * invl;
            AsT[(acol + 2) * 68 + arow + rr * 32] = v.z * invl;
            AsT[(acol + 3) * 68 + arow + rr * 32] = v.w * invl;
        }
#pragma unroll
        for (int rr = 0; rr < 2; rr++) {
            float4 v = *reinterpret_cast<const float4*>(&Wout[(size_t)(k0 + brow + rr * 16) * DMODEL + bn + bcol]);
            *reinterpret_cast<float4*>(&Bs[(brow + rr * 16) * 68 + bcol]) = v;
        }
        __syncthreads();
#pragma unroll
        for (int kk = 0; kk < 32; kk++) {
            float4 a = *reinterpret_cast<const float4*>(&AsT[kk * 68 + r0]);
            ulonglong2 b2 = *reinterpret_cast<const ulonglong2*>(&Bs[kk * 68 + c0]);
            unsigned long long as[4] = {splat2(a.x), splat2(a.y), splat2(a.z), splat2(a.w)};
#pragma unroll
            for (int i = 0; i < 4; i++) {
                acc2[i][0] = fma2(as[i], b2.x, acc2[i][0]);
                acc2[i][1] = fma2(as[i], b2.y, acc2[i][1]);
            }
        }
        __syncthreads();
    }
    float4 bb = *reinterpret_cast<const float4*>(&bout[bn + c0]);
#pragma unroll
    for (int i = 0; i < 4; i++) {
        float2 p0 = unpack2(acc2[i][0]);
        float2 p1 = unpack2(acc2[i][1]);
        float4 o = make_float4(p0.x + bb.x, p0.y + bb.y, p1.x + bb.z, p1.y + bb.w);
        *reinterpret_cast<float4*>(&C[(size_t)(bm + r0 + i) * DMODEL + bn + c0]) = o;
    }
}

// ---------------- launch ----------------
extern "C" void kernel_launch(void* const* d_in, const int* in_sizes, int n_in,
                              void* d_out, int out_size) {
    const float* x       = (const float*)d_in[0];
    const float* Wkkqvv  = (const float*)d_in[1];
    const float* bkkqvv  = (const float*)d_in[2];
    const float* WKq     = (const float*)d_in[3];
    const float* WVq     = (const float*)d_in[4];
    const float* Wout    = (const float*)d_in[5];
    const float* bout    = (const float*)d_in[6];
    float* out = (float*)d_out;

    float* proj_ptr = nullptr;
    cudaGetSymbolAddress((void**)&proj_ptr, g_proj);

    cudaFuncSetAttribute(attn_kernel, cudaFuncAttributeMaxDynamicSharedMemorySize, ATTN_SMEM_BYTES);

    zero_kernel<<<(NZERO + 255) / 256, 256>>>();
    gemm_nn_bias_kernel<<<dim3(NPROJ / 64, T_SEQ / 64), 256>>>(x, Wkkqvv, bkkqvv, proj_ptr,
                                                               T_SEQ, NPROJ, DMODEL);
    compute_M_kernel<<<dim3(64, 4, NH), 256>>>(WKq);
    attn_kernel<<<NH * T_SEQ * 2, 256, ATTN_SMEM_BYTES>>>();
    out_v_kernel<<<dim3(4, NH, 4), 256>>>(WVq);
    gemm_out_kernel<<<dim3(DMODEL / 64, T_SEQ / 64), 256>>>(Wout, bout, out);
}

// round 9
// speedup vs baseline: 1.8086x; 1.4485x over previous
#include <cuda_runtime.h>
#include <cstdint>

#define T_SEQ 256
#define NH 8
#define DHD 64
#define DMODEL 512
#define NPROJ 2560   // 5 * 512

// ---------------- packed fp32x2 helpers (Blackwell FFMA2) ----------------
__device__ __forceinline__ unsigned long long splat2(float x) {
    unsigned long long r;
    asm("mov.b64 %0, {%1, %1};" : "=l"(r) : "f"(x));
    return r;
}
__device__ __forceinline__ unsigned long long fma2(unsigned long long a, unsigned long long b,
                                                   unsigned long long c) {
    unsigned long long d;
    asm("fma.rn.f32x2 %0, %1, %2, %3;" : "=l"(d) : "l"(a), "l"(b), "l"(c));
    return d;
}
__device__ __forceinline__ float2 unpack2(unsigned long long v) {
    float2 f;
    asm("mov.b64 {%0, %1}, %2;" : "=f"(f.x), "=f"(f.y) : "l"(v));
    return f;
}

// ---------------- tf32 helpers ----------------
__device__ __forceinline__ uint32_t f2tf(float x) {
    uint32_t u;
    asm("cvt.rna.tf32.f32 %0, %1;" : "=r"(u) : "f"(x));
    return u;
}
__device__ __forceinline__ float f2tf_f(float x) { return __uint_as_float(f2tf(x)); }

__device__ __forceinline__ void mma8(float d[4], const uint32_t a[4], const uint32_t b[2]) {
    asm("mma.sync.aligned.m16n8k8.row.col.f32.tf32.tf32.f32 "
        "{%0,%1,%2,%3}, {%4,%5,%6,%7}, {%8,%9}, {%0,%1,%2,%3};"
        : "+f"(d[0]), "+f"(d[1]), "+f"(d[2]), "+f"(d[3])
        : "r"(a[0]), "r"(a[1]), "r"(a[2]), "r"(a[3]), "r"(b[0]), "r"(b[1]));
}

// ---------------- scratch ----------------
__device__ float g_proj[T_SEQ * NPROJ];            // [t, 2560]
__device__ float g_M[NH * T_SEQ * DHD * DHD];      // [n, q, k, j]
__device__ float g_Ga[NH * T_SEQ * DHD * DHD];     // [n, q, a, c] p-half 0
__device__ float g_Gb[NH * T_SEQ * DHD * DHD];     // [n, q, a, c] p-half 1
__device__ float g_l[2 * NH * T_SEQ];              // softmax denominator partials
__device__ float g_z[T_SEQ * DMODEL];              // [q, n*64+e] (unnormalized accum)

// ---------------- K0: zero z + l ----------------
#define NZERO (T_SEQ * DMODEL + 2 * NH * T_SEQ)
__global__ __launch_bounds__(256) void zero_kernel() {
    int i = blockIdx.x * 256 + threadIdx.x;
    if (i < T_SEQ * DMODEL) g_z[i] = 0.f;
    else g_l[i - T_SEQ * DMODEL] = 0.f;
}

// ---------------- K1: C[M,N] = A[M,K] @ B[K,N] + bias ----------------
__global__ __launch_bounds__(256) void gemm_nn_bias_kernel(
    const float* __restrict__ A, const float* __restrict__ B,
    const float* __restrict__ bias, float* __restrict__ C,
    int M, int N, int K) {
    __shared__ float AsT[32 * 68];
    __shared__ float Bs[32 * 68];
    const int tid = threadIdx.x;
    const int bm = blockIdx.y * 64;
    const int bn = blockIdx.x * 64;
    const int r0 = (tid & 15) * 4;
    const int c0 = (tid >> 4) * 4;
    const int arow = tid >> 3;
    const int acol = (tid & 7) * 4;
    const int brow = tid >> 4;
    const int bcol = (tid & 15) * 4;
    unsigned long long acc2[4][2] = {};
    for (int k0 = 0; k0 < K; k0 += 32) {
#pragma unroll
        for (int rr = 0; rr < 2; rr++) {
            int r = arow + rr * 32;
            float4 v = *reinterpret_cast<const float4*>(&A[(size_t)(bm + r) * K + k0 + acol]);
            AsT[(acol + 0) * 68 + r] = v.x; AsT[(acol + 1) * 68 + r] = v.y;
            AsT[(acol + 2) * 68 + r] = v.z; AsT[(acol + 3) * 68 + r] = v.w;
        }
#pragma unroll
        for (int rr = 0; rr < 2; rr++) {
            float4 v = *reinterpret_cast<const float4*>(&B[(size_t)(k0 + brow + rr * 16) * N + bn + bcol]);
            *reinterpret_cast<float4*>(&Bs[(brow + rr * 16) * 68 + bcol]) = v;
        }
        __syncthreads();
#pragma unroll
        for (int kk = 0; kk < 32; kk++) {
            float4 a = *reinterpret_cast<const float4*>(&AsT[kk * 68 + r0]);
            ulonglong2 b2 = *reinterpret_cast<const ulonglong2*>(&Bs[kk * 68 + c0]);
            unsigned long long as[4] = {splat2(a.x), splat2(a.y), splat2(a.z), splat2(a.w)};
#pragma unroll
            for (int i = 0; i < 4; i++) {
                acc2[i][0] = fma2(as[i], b2.x, acc2[i][0]);
                acc2[i][1] = fma2(as[i], b2.y, acc2[i][1]);
            }
        }
        __syncthreads();
    }
    float4 bb = *reinterpret_cast<const float4*>(&bias[bn + c0]);
#pragma unroll
    for (int i = 0; i < 4; i++) {
        float2 p0 = unpack2(acc2[i][0]);
        float2 p1 = unpack2(acc2[i][1]);
        float4 o = make_float4(p0.x + bb.x, p0.y + bb.y, p1.x + bb.z, p1.y + bb.w);
        *reinterpret_cast<float4*>(&C[(size_t)(bm + r0 + i) * N + bn + c0]) = o;
    }
}

// ---------------- K2: M[n,q,kj] = sum_i qproj[q,i] * Wkq[n,kj,i] ----------------
__global__ __launch_bounds__(256) void compute_M_kernel(const float* __restrict__ Wkq) {
    __shared__ float AsT[64 * 68];
    __shared__ float BsT[64 * 68];
    const int n = blockIdx.z;
    const int bq = blockIdx.y * 64;
    const int bkj = blockIdx.x * 64;
    const int tid = threadIdx.x;
    const int row = tid >> 4;
    const int col = (tid & 15) * 4;
#pragma unroll
    for (int rr = 0; rr < 4; rr++) {
        int r = row + rr * 16;
        float4 va = *reinterpret_cast<const float4*>(&g_proj[(size_t)(bq + r) * NPROJ + 1024 + n * 64 + col]);
        AsT[(col + 0) * 68 + r] = va.x; AsT[(col + 1) * 68 + r] = va.y;
        AsT[(col + 2) * 68 + r] = va.z; AsT[(col + 3) * 68 + r] = va.w;
        float4 vb = *reinterpret_cast<const float4*>(&Wkq[(size_t)n * 262144 + (size_t)(bkj + r) * 64 + col]);
        BsT[(col + 0) * 68 + r] = vb.x; BsT[(col + 1) * 68 + r] = vb.y;
        BsT[(col + 2) * 68 + r] = vb.z; BsT[(col + 3) * 68 + r] = vb.w;
    }
    __syncthreads();
    const int q0 = (tid & 15) * 4;
    const int kj0 = (tid >> 4) * 4;
    unsigned long long acc2[4][2] = {};
#pragma unroll 8
    for (int i = 0; i < 64; i++) {
        float4 a = *reinterpret_cast<const float4*>(&AsT[i * 68 + q0]);
        ulonglong2 b2 = *reinterpret_cast<const ulonglong2*>(&BsT[i * 68 + kj0]);
        unsigned long long as[4] = {splat2(a.x), splat2(a.y), splat2(a.z), splat2(a.w)};
#pragma unroll
        for (int ii = 0; ii < 4; ii++) {
            acc2[ii][0] = fma2(as[ii], b2.x, acc2[ii][0]);
            acc2[ii][1] = fma2(as[ii], b2.y, acc2[ii][1]);
        }
    }
#pragma unroll
    for (int ii = 0; ii < 4; ii++) {
        float2 p0 = unpack2(acc2[ii][0]);
        float2 p1 = unpack2(acc2[ii][1]);
        float4 o = make_float4(p0.x, p0.y, p1.x, p1.y);
        *reinterpret_cast<float4*>(&g_M[(size_t)(n * T_SEQ + bq + q0 + ii) * 4096 + bkj + kj0]) = o;
    }
}

// ---------------- K3: attention, 2 CTAs per (n,q) split by p-half ----------------
// smem (floats):
// U   [0, 8704): phase1 k1T (stride 129); phase2 k2s [t][j] s68 (4352) + v2T [c][t] s68 at 4352; phase3 v1s [128][64]
// BP  [8704, 17408): B p-major [p][j] stride 68 (tf32)
// ET  [17408, 26112): phase1 M (stride 64); phase2 E [p][t] stride 68 (tf32); phase3 RT [c][p] stride 130
// red [26112, 26120)
#define OFF_U   0
#define OFF_V2T 4352
#define OFF_BP  8704
#define OFF_ET  17408
#define OFF_RED 26112
#define ATTN_SMEM_FLOATS 26120
#define ATTN_SMEM_BYTES (ATTN_SMEM_FLOATS * 4)

// NI = ceil(p_count/32) in 1..4 (phases 1/3 only)
template <int NI>
__device__ __forceinline__ void attn_body(float* sm, int n, int q, int ph, int tid) {
    float* U   = sm + OFF_U;
    float* BP  = sm + OFF_BP;    // [p][j] stride 68
    float* ET  = sm + OFF_ET;
    float* red = sm + OFF_RED;

    const int P = q + 1;
    const int p_base = ph << 7;
    const int p_count = min(P - p_base, 128);
    const int pl = tid & 31;
    const int wid = tid >> 5;
    const int c8 = wid * 8;
    const int gid = pl >> 2;          // mma group id 0..7
    const int tidg = pl & 3;          // mma thread-in-group 0..3

    // ---- load M into ET region (stride 64) ----
    {
        const float* Mg = g_M + (size_t)(n * T_SEQ + q) * 4096;
        float* Ms = ET;
#pragma unroll
        for (int r = 0; r < 4; r++) {
            int off = (tid + r * 256) * 4;
            *reinterpret_cast<float4*>(&Ms[off]) = *reinterpret_cast<const float4*>(&Mg[off]);
        }
    }
    // ---- load k1 transposed [k][local p] (stride 129) ----
    {
        float* k1T = U;
        const int rr = tid >> 4;
        const int iv = (tid & 15) * 4;
#pragma unroll
        for (int pass = 0; pass < NI * 2; pass++) {
            int lp = pass * 16 + rr;
            int gp = p_base + lp;
            float4 v = make_float4(0.f, 0.f, 0.f, 0.f);
            if (lp < p_count) v = *reinterpret_cast<const float4*>(&g_proj[(size_t)gp * NPROJ + n * 64 + iv]);
            k1T[(iv + 0) * 129 + lp] = v.x;
            k1T[(iv + 1) * 129 + lp] = v.y;
            k1T[(iv + 2) * 129 + lp] = v.z;
            k1T[(iv + 3) * 129 + lp] = v.w;
        }
    }
    __syncthreads();

    // ---- phase 1 (FFMA2): B[p,j] = sum_k k1[p,k]*M[k,j]; store BP[p][j] as tf32 ----
    {
        const float* k1T = U;
        const float* Ms = ET;
        unsigned long long acc2[NI][4] = {};
#pragma unroll 4
        for (int k = 0; k < 64; k++) {
            unsigned long long a2[NI];
#pragma unroll
            for (int i = 0; i < NI; i++) a2[i] = splat2(k1T[k * 129 + pl + 32 * i]);
            const ulonglong2* bp = reinterpret_cast<const ulonglong2*>(&Ms[k * 64 + c8]);
            ulonglong2 b01 = bp[0], b23 = bp[1];
#pragma unroll
            for (int i = 0; i < NI; i++) {
                acc2[i][0] = fma2(a2[i], b01.x, acc2[i][0]);
                acc2[i][1] = fma2(a2[i], b01.y, acc2[i][1]);
                acc2[i][2] = fma2(a2[i], b23.x, acc2[i][2]);
                acc2[i][3] = fma2(a2[i], b23.y, acc2[i][3]);
            }
        }
#pragma unroll
        for (int m = 0; m < 4; m++)
#pragma unroll
            for (int i = 0; i < NI; i++) {
                float2 v = unpack2(acc2[i][m]);
                int p = pl + 32 * i;
                BP[p * 68 + c8 + 2 * m + 0] = f2tf_f(v.x);
                BP[p * 68 + c8 + 2 * m + 1] = f2tf_f(v.y);
            }
    }
    __syncthreads();

    // ---- phase 2 (tensor cores, tf32): stream t-tiles over [0, P) ----
    float rfr[2][4][4] = {};          // R fragments: warp tile 32p x 32c
    float lsum = 0.f;
    float* k2s = U;                   // [t][j] stride 68 (tf32)
    float* v2T = U + OFF_V2T;         // [c][t] stride 68 (tf32)
    const int s_t0w = (wid & 1) * 32, s_p0w = (wid >> 1) * 32;   // S warp tile 32t x 32p
    const int r_p0 = (wid & 3) * 32, r_c0 = (wid >> 2) * 32;     // R warp tile 32p x 32c
    for (int t0 = 0; t0 < P; t0 += 64) {
        // load k2 tile [t][j] (rows direct, converted)
        {
            const int rr = tid >> 4;
            const int iv = (tid & 15) * 4;
#pragma unroll
            for (int pass = 0; pass < 4; pass++) {
                int t = pass * 16 + rr;
                int gt = t0 + t;
                float4 a = make_float4(0.f, 0.f, 0.f, 0.f);
                if (gt < P) a = *reinterpret_cast<const float4*>(&g_proj[(size_t)gt * NPROJ + 512 + n * 64 + iv]);
                float4 c4 = make_float4(f2tf_f(a.x), f2tf_f(a.y), f2tf_f(a.z), f2tf_f(a.w));
                *reinterpret_cast<float4*>(&k2s[t * 68 + iv]) = c4;
            }
        }
        // load v2 tile transposed [c][t] (scalar coalesced gmem reads, converted)
        {
            const int c = tid & 63;
            const int tg4 = (tid >> 6) * 4;
#pragma unroll
            for (int it = 0; it < 4; it++) {
                int t4 = it * 16 + tg4;
                float4 c4;
                float* cf = &c4.x;
#pragma unroll
                for (int k = 0; k < 4; k++) {
                    int gt = t0 + t4 + k;
                    float v = (gt < P) ? g_proj[(size_t)gt * NPROJ + 2048 + n * 64 + c] : 0.f;
                    cf[k] = f2tf_f(v);
                }
                *reinterpret_cast<float4*>(&v2T[c * 68 + t4]) = c4;
            }
        }
        __syncthreads();
        // ---- S^T mma: D[t][p] = sum_j k2[t][j] * B[p][j] ----
        {
            float sfr[2][4][4] = {};
#pragma unroll
            for (int k = 0; k < 8; k++) {
                const int j0 = k * 8;
                uint32_t afr[2][4], bfr[4][2];
#pragma unroll
                for (int mt = 0; mt < 2; mt++) {
                    int tb = s_t0w + mt * 16;
                    afr[mt][0] = __float_as_uint(k2s[(tb + gid) * 68 + j0 + tidg]);
                    afr[mt][1] = __float_as_uint(k2s[(tb + gid + 8) * 68 + j0 + tidg]);
                    afr[mt][2] = __float_as_uint(k2s[(tb + gid) * 68 + j0 + tidg + 4]);
                    afr[mt][3] = __float_as_uint(k2s[(tb + gid + 8) * 68 + j0 + tidg + 4]);
                }
#pragma unroll
                for (int nt = 0; nt < 4; nt++) {
                    int pb = s_p0w + nt * 8 + gid;
                    bfr[nt][0] = __float_as_uint(BP[pb * 68 + j0 + tidg]);
                    bfr[nt][1] = __float_as_uint(BP[pb * 68 + j0 + tidg + 4]);
                }
#pragma unroll
                for (int mt = 0; mt < 2; mt++)
#pragma unroll
                    for (int nt = 0; nt < 4; nt++)
                        mma8(sfr[mt][nt], afr[mt], bfr[nt]);
            }
            // exp + mask + store ET[p][t] (tf32)
#pragma unroll
            for (int mt = 0; mt < 2; mt++)
#pragma unroll
                for (int nt = 0; nt < 4; nt++)
#pragma unroll
                    for (int r = 0; r < 4; r++) {
                        int t_loc = s_t0w + mt * 16 + gid + ((r >> 1) << 3);
                        int p_loc = s_p0w + nt * 8 + 2 * tidg + (r & 1);
                        int gt = t0 + t_loc;
                        int gp = p_base + p_loc;
                        float e = (gp < P && gt < P) ? __expf(sfr[mt][nt][r] * 0.015625f) : 0.f;
                        lsum += e;
                        ET[p_loc * 68 + t_loc] = f2tf_f(e);
                    }
        }
        __syncthreads();
        // ---- R mma: R[p][c] += sum_t E[p][t] * v2[t][c] ----
        {
#pragma unroll
            for (int k = 0; k < 8; k++) {
                const int t8 = k * 8;
                uint32_t afr[2][4], bfr[4][2];
#pragma unroll
                for (int mt = 0; mt < 2; mt++) {
                    int pb = r_p0 + mt * 16;
                    afr[mt][0] = __float_as_uint(ET[(pb + gid) * 68 + t8 + tidg]);
                    afr[mt][1] = __float_as_uint(ET[(pb + gid + 8) * 68 + t8 + tidg]);
                    afr[mt][2] = __float_as_uint(ET[(pb + gid) * 68 + t8 + tidg + 4]);
                    afr[mt][3] = __float_as_uint(ET[(pb + gid + 8) * 68 + t8 + tidg + 4]);
                }
#pragma unroll
                for (int nt = 0; nt < 4; nt++) {
                    int cb = r_c0 + nt * 8 + gid;
                    bfr[nt][0] = __float_as_uint(v2T[cb * 68 + t8 + tidg]);
                    bfr[nt][1] = __float_as_uint(v2T[cb * 68 + t8 + tidg + 4]);
                }
#pragma unroll
                for (int mt = 0; mt < 2; mt++)
#pragma unroll
                    for (int nt = 0; nt < 4; nt++)
                        mma8(rfr[mt][nt], afr[mt], bfr[nt]);
            }
        }
        __syncthreads();
    }

    // ---- stage RT[c][p] (stride 130) into ET region; load v1 rows into U ----
    {
        float* RT = ET;
#pragma unroll
        for (int mt = 0; mt < 2; mt++)
#pragma unroll
            for (int nt = 0; nt < 4; nt++)
#pragma unroll
                for (int r = 0; r < 4; r++) {
                    int p = r_p0 + mt * 16 + gid + ((r >> 1) << 3);
                    int c = r_c0 + nt * 8 + 2 * tidg + (r & 1);
                    RT[c * 130 + p] = rfr[mt][nt][r];
                }
    }
    {
        float* v1s = U;   // [128][64]
        const int rr = tid >> 4;
        const int iv = (tid & 15) * 4;
#pragma unroll
        for (int pass = 0; pass < NI * 2; pass++) {
            int lp = pass * 16 + rr;
            if (lp < p_count) {
                float4 v = *reinterpret_cast<const float4*>(
                    &g_proj[(size_t)(p_base + lp) * NPROJ + 1536 + n * 64 + iv]);
                *reinterpret_cast<float4*>(&v1s[lp * 64 + iv]) = v;
            }
        }
    }
    // lsum reduce
#pragma unroll
    for (int off = 16; off > 0; off >>= 1)
        lsum += __shfl_xor_sync(0xffffffffu, lsum, off);
    if (pl == 0) red[wid] = lsum;
    __syncthreads();
    if (tid == 0) {
        float total = 0.f;
#pragma unroll
        for (int w = 0; w < 8; w++) total += red[w];
        g_l[ph * (NH * T_SEQ) + n * T_SEQ + q] = total;
    }

    // ---- phase 3 (FFMA2 fp32): G[a,c] = sum_{lp<p_count} v1[lp,a] * RT[c,lp] ----
    {
        const float* v1s = U;
        const float* RT = ET;
        const int a0 = (tid & 15) * 4;
        const int c0 = (tid >> 4) * 4;
        unsigned long long acc2[2][4] = {};
#pragma unroll 4
        for (int p = 0; p < p_count; p++) {
            ulonglong2 av2 = *reinterpret_cast<const ulonglong2*>(&v1s[p * 64 + a0]);
#pragma unroll
            for (int k = 0; k < 4; k++) {
                unsigned long long r2 = splat2(RT[(c0 + k) * 130 + p]);
                acc2[0][k] = fma2(av2.x, r2, acc2[0][k]);
                acc2[1][k] = fma2(av2.y, r2, acc2[1][k]);
            }
        }
        float* Gout = (ph ? g_Gb : g_Ga) + (size_t)(n * T_SEQ + q) * 4096;
#pragma unroll
        for (int h = 0; h < 2; h++) {
            float2 v0 = unpack2(acc2[h][0]);
            float2 v1 = unpack2(acc2[h][1]);
            float2 v2 = unpack2(acc2[h][2]);
            float2 v3 = unpack2(acc2[h][3]);
            float4 lo = make_float4(v0.x, v1.x, v2.x, v3.x);
            float4 hi = make_float4(v0.y, v1.y, v2.y, v3.y);
            *reinterpret_cast<float4*>(&Gout[(a0 + 2 * h + 0) * 64 + c0]) = lo;
            *reinterpret_cast<float4*>(&Gout[(a0 + 2 * h + 1) * 64 + c0]) = hi;
        }
    }
}

__global__ __launch_bounds__(256, 2) void attn_kernel() {
    extern __shared__ float sm[];
    const int bid = blockIdx.x;
    const int q = 255 - (bid >> 4);
    const int n = (bid >> 1) & 7;
    const int ph = bid & 1;
    const int P = q + 1;
    const int p_count = P - (ph << 7);
    if (p_count <= 0) return;
    const int ni = (min(p_count, 128) + 31) >> 5;
    switch (ni) {
        case 1: attn_body<1>(sm, n, q, ph, threadIdx.x); break;
        case 2: attn_body<2>(sm, n, q, ph, threadIdx.x); break;
        case 3: attn_body<3>(sm, n, q, ph, threadIdx.x); break;
        default: attn_body<4>(sm, n, q, ph, threadIdx.x); break;
    }
}

// ---------------- K4: z_raw += (Ga+Gb) @ W_Vq (K-split, atomics) ----------------
__global__ __launch_bounds__(256) void out_v_kernel(const float* __restrict__ Wvq) {
    __shared__ float AsT[32 * 68];
    __shared__ float Bs[32 * 68];
    const int n = blockIdx.y;
    const int bq = blockIdx.x * 64;
    const int ks = blockIdx.z;
    const int tid = threadIdx.x;
    const bool two = (bq >= 128);
    const int arow = tid >> 3, acol = (tid & 7) * 4;
    const int brow = tid >> 4, bcol = (tid & 15) * 4;
    const int q0 = (tid & 15) * 4, e0 = (tid >> 4) * 4;
    unsigned long long acc2[4][2] = {};
    for (int k0 = ks * 1024; k0 < ks * 1024 + 1024; k0 += 32) {
#pragma unroll
        for (int rr = 0; rr < 2; rr++) {
            int r = arow + rr * 32;
            size_t idx = (size_t)(n * T_SEQ + bq + r) * 4096 + k0 + acol;
            float4 v = *reinterpret_cast<const float4*>(&g_Ga[idx]);
            if (two) {
                float4 w = *reinterpret_cast<const float4*>(&g_Gb[idx]);
                v.x += w.x; v.y += w.y; v.z += w.z; v.w += w.w;
            }
            AsT[(acol + 0) * 68 + r] = v.x; AsT[(acol + 1) * 68 + r] = v.y;
            AsT[(acol + 2) * 68 + r] = v.z; AsT[(acol + 3) * 68 + r] = v.w;
        }
#pragma unroll
        for (int rr = 0; rr < 2; rr++) {
            float4 v = *reinterpret_cast<const float4*>(
                &Wvq[(size_t)n * 262144 + (size_t)(k0 + brow + rr * 16) * 64 + bcol]);
            *reinterpret_cast<float4*>(&Bs[(brow + rr * 16) * 68 + bcol]) = v;
        }
        __syncthreads();
#pragma unroll
        for (int kk = 0; kk < 32; kk++) {
            float4 a = *reinterpret_cast<const float4*>(&AsT[kk * 68 + q0]);
            ulonglong2 b2 = *reinterpret_cast<const ulonglong2*>(&Bs[kk * 68 + e0]);
            unsigned long long as[4] = {splat2(a.x), splat2(a.y), splat2(a.z), splat2(a.w)};
#pragma unroll
            for (int i = 0; i < 4; i++) {
                acc2[i][0] = fma2(as[i], b2.x, acc2[i][0]);
                acc2[i][1] = fma2(as[i], b2.y, acc2[i][1]);
            }
        }
        __syncthreads();
    }
#pragma unroll
    for (int i = 0; i < 4; i++) {
        float2 p0 = unpack2(acc2[i][0]);
        float2 p1 = unpack2(acc2[i][1]);
        float* zp = &g_z[(size_t)(bq + q0 + i) * DMODEL + n * 64 + e0];
        atomicAdd(zp + 0, p0.x);
        atomicAdd(zp + 1, p0.y);
        atomicAdd(zp + 2, p1.x);
        atomicAdd(zp + 3, p1.y);
    }
}

// ---------------- K5: out = (z_raw * 1/(la+lb)) @ W_out + b_out ----------------
__global__ __launch_bounds__(256) void gemm_out_kernel(
    const float* __restrict__ Wout, const float* __restrict__ bout, float* __restrict__ C) {
    __shared__ float AsT[32 * 68];
    __shared__ float Bs[32 * 68];
    const int tid = threadIdx.x;
    const int bm = blockIdx.y * 64;
    const int bn = blockIdx.x * 64;
    const int r0 = (tid & 15) * 4;
    const int c0 = (tid >> 4) * 4;
    const int arow = tid >> 3, acol = (tid & 7) * 4;
    const int brow = tid >> 4, bcol = (tid & 15) * 4;
    unsigned long long acc2[4][2] = {};
    for (int k0 = 0; k0 < DMODEL; k0 += 32) {
#pragma unroll
        for (int rr = 0; rr < 2; rr++) {
            int r = bm + arow + rr * 32;
            int gk = k0 + acol;
            int li = (gk >> 6) * T_SEQ + r;
            float invl = 1.f / (g_l[li] + g_l[NH * T_SEQ + li]);
            float4 v = *reinterpret_cast<const float4*>(&g_z[(size_t)r * DMODEL + gk]);
            AsT[(acol + 0) * 68 + arow + rr * 32] = v.x * invl;
            AsT[(acol + 1) * 68 + arow + rr * 32] = v.y * invl;
            AsT[(acol + 2) * 68 + arow + rr * 32] = v.z * invl;
            AsT[(acol + 3) * 68 + arow + rr * 32] = v.w * invl;
        }
#pragma unroll
        for (int rr = 0; rr < 2; rr++) {
            float4 v = *reinterpret_cast<const float4*>(&Wout[(size_t)(k0 + brow + rr * 16) * DMODEL + bn + bcol]);
            *reinterpret_cast<float4*>(&Bs[(brow + rr * 16) * 68 + bcol]) = v;
        }
        __syncthreads();
#pragma unroll
        for (int kk = 0; kk < 32; kk++) {
            float4 a = *reinterpret_cast<const float4*>(&AsT[kk * 68 + r0]);
            ulonglong2 b2 = *reinterpret_cast<const ulonglong2*>(&Bs[kk * 68 + c0]);
            unsigned long long as[4] = {splat2(a.x), splat2(a.y), splat2(a.z), splat2(a.w)};
#pragma unroll
            for (int i = 0; i < 4; i++) {
                acc2[i][0] = fma2(as[i], b2.x, acc2[i][0]);
                acc2[i][1] = fma2(as[i], b2.y, acc2[i][1]);
            }
        }
        __syncthreads();
    }
    float4 bb = *reinterpret_cast<const float4*>(&bout[bn + c0]);
#pragma unroll
    for (int i = 0; i < 4; i++) {
        float2 p0 = unpack2(acc2[i][0]);
        float2 p1 = unpack2(acc2[i][1]);
        float4 o = make_float4(p0.x + bb.x, p0.y + bb.y, p1.x + bb.z, p1.y + bb.w);
        *reinterpret_cast<float4*>(&C[(size_t)(bm + r0 + i) * DMODEL + bn + c0]) = o;
    }
}

// ---------------- launch ----------------
extern "C" void kernel_launch(void* const* d_in, const int* in_sizes, int n_in,
                              void* d_out, int out_size) {
    const float* x       = (const float*)d_in[0];
    const float* Wkkqvv  = (const float*)d_in[1];
    const float* bkkqvv  = (const float*)d_in[2];
    const float* WKq     = (const float*)d_in[3];
    const float* WVq     = (const float*)d_in[4];
    const float* Wout    = (const float*)d_in[5];
    const float* bout    = (const float*)d_in[6];
    float* out = (float*)d_out;

    float* proj_ptr = nullptr;
    cudaGetSymbolAddress((void**)&proj_ptr, g_proj);

    cudaFuncSetAttribute(attn_kernel, cudaFuncAttributeMaxDynamicSharedMemorySize, ATTN_SMEM_BYTES);

    zero_kernel<<<(NZERO + 255) / 256, 256>>>();
    gemm_nn_bias_kernel<<<dim3(NPROJ / 64, T_SEQ / 64), 256>>>(x, Wkkqvv, bkkqvv, proj_ptr,
                                                               T_SEQ, NPROJ, DMODEL);
    compute_M_kernel<<<dim3(64, 4, NH), 256>>>(WKq);
    attn_kernel<<<NH * T_SEQ * 2, 256, ATTN_SMEM_BYTES>>>();
    out_v_kernel<<<dim3(4, NH, 4), 256>>>(WVq);
    gemm_out_kernel<<<dim3(DMODEL / 64, T_SEQ / 64), 256>>>(Wout, bout, out);
}